// round 6
// baseline (speedup 1.0000x reference)
#include <cuda_runtime.h>
#include <cuda_bf16.h>
#include <cstdint>
#include <math.h>

#define BATCH 4
#define SEQ   2048
#define DMODEL 1024

// ---------------- device scratch ----------------
__device__ __nv_bfloat16 g_x1[8388608],  g_x2[8388608];    // x planes  [8192][1024]
__device__ __nv_bfloat16 g_wqt1[1048576], g_wqt2[1048576]; // W^T planes [n][k]
__device__ __nv_bfloat16 g_wkt1[1048576], g_wkt2[1048576];
__device__ __nv_bfloat16 g_wvt1[1048576], g_wvt2[1048576];
__device__ __nv_bfloat16 g_q1[8388608],  g_q2[8388608];
__device__ __nv_bfloat16 g_k1[8388608],  g_k2[8388608];
__device__ __nv_bfloat16 g_vt1[8388608], g_vt2[8388608];   // V^T planes [b][1024][2048]
__device__ float         g_s[16777216];                    // scores fp32
__device__ __nv_bfloat16 g_p1[16777216], g_p2[16777216];   // prob planes

// ---------------- helpers ----------------
__device__ __forceinline__ uint32_t smem_u32(const void* p) {
    uint32_t a;
    asm("{ .reg .u64 t; cvta.to.shared.u64 t, %1; cvt.u32.u64 %0, t; }" : "=r"(a) : "l"(p));
    return a;
}
__device__ __forceinline__ void cp_async16(uint32_t d, const void* s) {
    asm volatile("cp.async.cg.shared.global [%0], [%1], 16;" :: "r"(d), "l"(s) : "memory");
}
#define CP_COMMIT() asm volatile("cp.async.commit_group;" ::: "memory")
#define CP_WAIT1()  asm volatile("cp.async.wait_group 1;" ::: "memory")
#define CP_WAIT0()  asm volatile("cp.async.wait_group 0;" ::: "memory")

__device__ __forceinline__ void ldsm4(uint32_t* r, uint32_t a) {
    asm volatile("ldmatrix.sync.aligned.m8n8.x4.shared.b16 {%0,%1,%2,%3}, [%4];"
        : "=r"(r[0]), "=r"(r[1]), "=r"(r[2]), "=r"(r[3]) : "r"(a));
}
__device__ __forceinline__ void mma_bf16(float* c, const uint32_t* a, const uint32_t* b) {
    asm volatile("mma.sync.aligned.m16n8k16.row.col.f32.bf16.bf16.f32 "
        "{%0,%1,%2,%3}, {%4,%5,%6,%7}, {%8,%9}, {%0,%1,%2,%3};"
        : "+f"(c[0]), "+f"(c[1]), "+f"(c[2]), "+f"(c[3])
        : "r"(a[0]), "r"(a[1]), "r"(a[2]), "r"(a[3]), "r"(b[0]), "r"(b[1]));
}
__device__ __forceinline__ void split_pack(float a, float b, uint32_t& hi, uint32_t& lo) {
    __nv_bfloat16 ha = __float2bfloat16(a), hb = __float2bfloat16(b);
    __nv_bfloat16 ra = __float2bfloat16(a - __bfloat162float(ha));
    __nv_bfloat16 rb = __float2bfloat16(b - __bfloat162float(hb));
    __nv_bfloat162 h = __halves2bfloat162(ha, hb);
    __nv_bfloat162 r = __halves2bfloat162(ra, rb);
    hi = *reinterpret_cast<uint32_t*>(&h);
    lo = *reinterpret_cast<uint32_t*>(&r);
}

// ---------------- prep kernels ----------------
__global__ __launch_bounds__(256) void split2_kernel(const float4* __restrict__ X,
                                                     uint2* __restrict__ X1, uint2* __restrict__ X2, int n4) {
    int i = blockIdx.x * 256 + threadIdx.x;
    if (i >= n4) return;
    float4 v = X[i];
    uint2 u1, u2;
    split_pack(v.x, v.y, u1.x, u2.x);
    split_pack(v.z, v.w, u1.y, u2.y);
    X1[i] = u1; X2[i] = u2;
}

__global__ __launch_bounds__(256) void wtrans_split3_kernel(
    const float* __restrict__ Wq, const float* __restrict__ Wk, const float* __restrict__ Wv,
    __nv_bfloat16* __restrict__ Tq1, __nv_bfloat16* __restrict__ Tq2,
    __nv_bfloat16* __restrict__ Tk1, __nv_bfloat16* __restrict__ Tk2,
    __nv_bfloat16* __restrict__ Tv1, __nv_bfloat16* __restrict__ Tv2)
{
    const float* W = (blockIdx.z == 0) ? Wq : (blockIdx.z == 1) ? Wk : Wv;
    __nv_bfloat16* T1 = (blockIdx.z == 0) ? Tq1 : (blockIdx.z == 1) ? Tk1 : Tv1;
    __nv_bfloat16* T2 = (blockIdx.z == 0) ? Tq2 : (blockIdx.z == 1) ? Tk2 : Tv2;

    __shared__ float t[32][33];
    int k0 = blockIdx.y * 32, n0 = blockIdx.x * 32;
    int tx = threadIdx.x & 31, ty = threadIdx.x >> 5;
    #pragma unroll
    for (int i = 0; i < 4; i++) {
        int k = ty + i * 8;
        t[k][tx] = W[(long long)(k0 + k) * DMODEL + n0 + tx];
    }
    __syncthreads();
    #pragma unroll
    for (int i = 0; i < 4; i++) {
        int n = ty + i * 8;
        float v = t[tx][n];
        __nv_bfloat16 h = __float2bfloat16(v);
        long long idx = (long long)(n0 + n) * DMODEL + k0 + tx;
        T1[idx] = h;
        T2[idx] = __float2bfloat16(v - __bfloat162float(h));
    }
}

// ---------------- GEMM: C = scale*(A·B^T)(+bias); A[M,K], B[N,K] bf16 2-plane ----------------
#define KC 32
#define TROW 80                      // bytes per smem row (32 bf16 + pad 8)
#define TILE_B (128 * TROW)          // 10240
#define STAGE_B (4 * TILE_B)         // 40960
#define DSMEM (2 * STAGE_B)          // 81920

template<int MODE, bool HAS_BIAS>
__global__ __launch_bounds__(256, 2)
void gemm_mma(const __nv_bfloat16* __restrict__ A1, const __nv_bfloat16* __restrict__ A2, int ldA, long long sA,
              const __nv_bfloat16* __restrict__ B1, const __nv_bfloat16* __restrict__ B2, int ldB, long long sB,
              const float* __restrict__ bias,
              float* __restrict__ C, __nv_bfloat16* __restrict__ C1, __nv_bfloat16* __restrict__ C2,
              int ldC, long long sC, float scale, int K)
{
    extern __shared__ char smem[];
    const uint32_t sbase = smem_u32(smem);

    const int tid = threadIdx.x, lane = tid & 31, wid = tid >> 5;
    const int wm = wid & 3, wn = wid >> 2;
    const long long z = blockIdx.z;
    A1 += z * sA; A2 += z * sA; B1 += z * sB; B2 += z * sB;
    if (MODE == 0) C += z * sC;
    const int m0 = blockIdx.y * 128, n0 = blockIdx.x * 128;

    // ---- precomputed load-side pointers (per-thread, fixed across chunks) ----
    const int lrow = tid >> 2, lseg = tid & 3;
    const uint32_t lso = lrow * TROW + lseg * 16;               // smem offset within tile
    const __nv_bfloat16* gA1 = A1 + (long long)(m0 + lrow) * ldA + lseg * 8;
    const __nv_bfloat16* gA2 = A2 + (long long)(m0 + lrow) * ldA + lseg * 8;
    const __nv_bfloat16* gB1 = B1 + (long long)(n0 + lrow) * ldB + lseg * 8;
    const __nv_bfloat16* gB2 = B2 + (long long)(n0 + lrow) * ldB + lseg * 8;
    const __nv_bfloat16* gA1b = A1 + (long long)(m0 + 64 + lrow) * ldA + lseg * 8;
    const __nv_bfloat16* gA2b = A2 + (long long)(m0 + 64 + lrow) * ldA + lseg * 8;
    const __nv_bfloat16* gB1b = B1 + (long long)(n0 + 64 + lrow) * ldB + lseg * 8;
    const __nv_bfloat16* gB2b = B2 + (long long)(n0 + 64 + lrow) * ldB + lseg * 8;
    const uint32_t lsob = (64 + lrow) * TROW + lseg * 16;

    auto load_stage = [&](int stg, int k0) {
        const uint32_t st = sbase + stg * STAGE_B;
        cp_async16(st + 0 * TILE_B + lso,  gA1 + k0);
        cp_async16(st + 1 * TILE_B + lso,  gA2 + k0);
        cp_async16(st + 2 * TILE_B + lso,  gB1 + k0);
        cp_async16(st + 3 * TILE_B + lso,  gB2 + k0);
        cp_async16(st + 0 * TILE_B + lsob, gA1b + k0);
        cp_async16(st + 1 * TILE_B + lsob, gA2b + k0);
        cp_async16(st + 2 * TILE_B + lsob, gB1b + k0);
        cp_async16(st + 3 * TILE_B + lsob, gB2b + k0);
    };

    // ---- precomputed ldsm base offsets (within a stage) ----
    const uint32_t khalf = ((lane >> 4) << 3) * 2;
    const uint32_t arow0 = (wm * 32 + (lane & 15)) * TROW + khalf;
    const uint32_t brow0 = (wn * 64 + (lane & 15)) * TROW + khalf;

    float acc[2][8][4] = {};

    const int CH = K / KC;
    load_stage(0, 0);  CP_COMMIT();
    load_stage(1, KC); CP_COMMIT();

    for (int c = 0; c < CH; c++) {
        if (c + 1 < CH) CP_WAIT1(); else CP_WAIT0();
        __syncthreads();
        const uint32_t st = sbase + (c & 1) * STAGE_B;

        #pragma unroll
        for (int ks = 0; ks < 2; ks++) {
            const uint32_t arow = st + arow0 + ks * 32;
            const uint32_t brow = st + brow0 + ks * 32;

            // load a0, a1, b0 (max 3 fragment sets live -> no spills)
            uint32_t a0[2][4], a1[2][4], bb[8][2];
            #pragma unroll
            for (int mt = 0; mt < 2; mt++) {
                ldsm4(a0[mt], 0 * TILE_B + arow + mt * 16 * TROW);
                ldsm4(a1[mt], 1 * TILE_B + arow + mt * 16 * TROW);
            }
            #pragma unroll
            for (int nt2 = 0; nt2 < 4; nt2++) {
                uint32_t r[4];
                ldsm4(r, 2 * TILE_B + brow + nt2 * 16 * TROW);
                bb[nt2 * 2 + 0][0] = r[0]; bb[nt2 * 2 + 0][1] = r[2];
                bb[nt2 * 2 + 1][0] = r[1]; bb[nt2 * 2 + 1][1] = r[3];
            }
            // pass 0: a0 * b0
            #pragma unroll
            for (int mt = 0; mt < 2; mt++)
                #pragma unroll
                for (int nt = 0; nt < 8; nt++)
                    mma_bf16(acc[mt][nt], a0[mt], bb[nt]);
            // pass 1: a1 * b0   (a1 and b0 die after this)
            #pragma unroll
            for (int mt = 0; mt < 2; mt++)
                #pragma unroll
                for (int nt = 0; nt < 8; nt++)
                    mma_bf16(acc[mt][nt], a1[mt], bb[nt]);
            // reload bb with B plane 1 (reuses b0's registers)
            #pragma unroll
            for (int nt2 = 0; nt2 < 4; nt2++) {
                uint32_t r[4];
                ldsm4(r, 3 * TILE_B + brow + nt2 * 16 * TROW);
                bb[nt2 * 2 + 0][0] = r[0]; bb[nt2 * 2 + 0][1] = r[2];
                bb[nt2 * 2 + 1][0] = r[1]; bb[nt2 * 2 + 1][1] = r[3];
            }
            // pass 2: a0 * b1
            #pragma unroll
            for (int mt = 0; mt < 2; mt++)
                #pragma unroll
                for (int nt = 0; nt < 8; nt++)
                    mma_bf16(acc[mt][nt], a0[mt], bb[nt]);
        }
        __syncthreads();
        if (c + 2 < CH) { load_stage(c & 1, (c + 2) * KC); }
        CP_COMMIT();
    }
    __syncthreads();

    // ---------------- epilogue ----------------
    if (MODE == 2) {
        float* stg = (float*)smem;     // [128][133]
        #pragma unroll
        for (int mt = 0; mt < 2; mt++)
            #pragma unroll
            for (int h = 0; h < 2; h++) {
                int m = wm * 32 + mt * 16 + (lane >> 2) + h * 8;
                #pragma unroll
                for (int nt = 0; nt < 8; nt++) {
                    int n = wn * 64 + nt * 8 + ((lane & 3) << 1);
                    float v0 = acc[mt][nt][h * 2 + 0] * scale;
                    float v1 = acc[mt][nt][h * 2 + 1] * scale;
                    if (HAS_BIAS) { v0 += __ldg(bias + n0 + n); v1 += __ldg(bias + n0 + n + 1); }
                    stg[m * 133 + n] = v0;
                    stg[m * 133 + n + 1] = v1;
                }
            }
        __syncthreads();
        #pragma unroll 4
        for (int i = 0; i < 64; i++) {
            int linear = i * 256 + tid;       // 0..16383
            int n = linear >> 7, m = linear & 127;
            float v = stg[m * 133 + n];
            int gm = m0 + m;
            long long idx = ((long long)(gm >> 11) * DMODEL + (n0 + n)) * SEQ + (gm & (SEQ - 1));
            __nv_bfloat16 hh = __float2bfloat16(v);
            C1[idx] = hh;
            C2[idx] = __float2bfloat16(v - __bfloat162float(hh));
        }
    } else {
        #pragma unroll
        for (int mt = 0; mt < 2; mt++)
            #pragma unroll
            for (int h = 0; h < 2; h++) {
                int m = m0 + wm * 32 + mt * 16 + (lane >> 2) + h * 8;
                #pragma unroll
                for (int nt = 0; nt < 8; nt++) {
                    int n = n0 + wn * 64 + nt * 8 + ((lane & 3) << 1);
                    float v0 = acc[mt][nt][h * 2 + 0] * scale;
                    float v1 = acc[mt][nt][h * 2 + 1] * scale;
                    if (HAS_BIAS) { v0 += __ldg(bias + n); v1 += __ldg(bias + n + 1); }
                    if (MODE == 0) {
                        float2 f; f.x = v0; f.y = v1;
                        *(float2*)(C + (long long)m * ldC + n) = f;
                    } else {
                        uint32_t u1, u2;
                        split_pack(v0, v1, u1, u2);
                        *(uint32_t*)(C1 + (long long)m * ldC + n) = u1;
                        *(uint32_t*)(C2 + (long long)m * ldC + n) = u2;
                    }
                }
            }
    }
}

// ---------------- softmax: fp32 scores -> bf16 prob planes ----------------
__global__ __launch_bounds__(256) void softmax_planes_kernel(const float* __restrict__ S,
                                                             __nv_bfloat16* __restrict__ P1,
                                                             __nv_bfloat16* __restrict__ P2) {
    const long long row = blockIdx.x;
    const float* p = S + row * SEQ;
    const int tid = threadIdx.x, lane = tid & 31, w = tid >> 5;
    __shared__ float red[8];

    float vals[8];
    const float4 a = *(const float4*)(p + tid * 8);
    const float4 b = *(const float4*)(p + tid * 8 + 4);
    vals[0]=a.x; vals[1]=a.y; vals[2]=a.z; vals[3]=a.w;
    vals[4]=b.x; vals[5]=b.y; vals[6]=b.z; vals[7]=b.w;

    float m = -INFINITY;
    #pragma unroll
    for (int i = 0; i < 8; i++) m = fmaxf(m, vals[i]);
    #pragma unroll
    for (int o = 16; o; o >>= 1) m = fmaxf(m, __shfl_xor_sync(0xffffffffu, m, o));
    if (lane == 0) red[w] = m;
    __syncthreads();
    if (w == 0) {
        float x = red[lane & 7];
        #pragma unroll
        for (int o = 4; o; o >>= 1) x = fmaxf(x, __shfl_xor_sync(0xffffffffu, x, o));
        if (lane == 0) red[0] = x;
    }
    __syncthreads();
    m = red[0];
    __syncthreads();

    float s = 0.0f;
    #pragma unroll
    for (int i = 0; i < 8; i++) { vals[i] = __expf(vals[i] - m); s += vals[i]; }
    #pragma unroll
    for (int o = 16; o; o >>= 1) s += __shfl_xor_sync(0xffffffffu, s, o);
    if (lane == 0) red[w] = s;
    __syncthreads();
    if (w == 0) {
        float x = red[lane & 7];
        #pragma unroll
        for (int o = 4; o; o >>= 1) x += __shfl_xor_sync(0xffffffffu, x, o);
        if (lane == 0) red[0] = x;
    }
    __syncthreads();
    const float inv = 1.0f / red[0];

    uint4 u1, u2;
    split_pack(vals[0]*inv, vals[1]*inv, u1.x, u2.x);
    split_pack(vals[2]*inv, vals[3]*inv, u1.y, u2.y);
    split_pack(vals[4]*inv, vals[5]*inv, u1.z, u2.z);
    split_pack(vals[6]*inv, vals[7]*inv, u1.w, u2.w);
    *(uint4*)(P1 + row * SEQ + tid * 8) = u1;
    *(uint4*)(P2 + row * SEQ + tid * 8) = u2;
}

// ---------------- launch ----------------
extern "C" void kernel_launch(void* const* d_in, const int* in_sizes, int n_in,
                              void* d_out, int out_size)
{
    const float* x  = (const float*)d_in[0];
    const float* Wq = (const float*)d_in[1];
    const float* bq = (const float*)d_in[2];
    const float* Wk = (const float*)d_in[3];
    const float* bk = (const float*)d_in[4];
    const float* Wv = (const float*)d_in[5];
    const float* bv = (const float*)d_in[6];
    float* out = (float*)d_out;

    void *x1, *x2, *wqt1, *wqt2, *wkt1, *wkt2, *wvt1, *wvt2;
    void *q1, *q2, *k1, *k2, *vt1, *vt2, *s, *p1, *p2;
    cudaGetSymbolAddress(&x1, g_x1);   cudaGetSymbolAddress(&x2, g_x2);
    cudaGetSymbolAddress(&wqt1, g_wqt1); cudaGetSymbolAddress(&wqt2, g_wqt2);
    cudaGetSymbolAddress(&wkt1, g_wkt1); cudaGetSymbolAddress(&wkt2, g_wkt2);
    cudaGetSymbolAddress(&wvt1, g_wvt1); cudaGetSymbolAddress(&wvt2, g_wvt2);
    cudaGetSymbolAddress(&q1, g_q1);   cudaGetSymbolAddress(&q2, g_q2);
    cudaGetSymbolAddress(&k1, g_k1);   cudaGetSymbolAddress(&k2, g_k2);
    cudaGetSymbolAddress(&vt1, g_vt1); cudaGetSymbolAddress(&vt2, g_vt2);
    cudaGetSymbolAddress(&s, g_s);
    cudaGetSymbolAddress(&p1, g_p1);   cudaGetSymbolAddress(&p2, g_p2);

    cudaFuncSetAttribute(gemm_mma<0, false>, cudaFuncAttributeMaxDynamicSharedMemorySize, DSMEM);
    cudaFuncSetAttribute(gemm_mma<1, true >, cudaFuncAttributeMaxDynamicSharedMemorySize, DSMEM);
    cudaFuncSetAttribute(gemm_mma<2, true >, cudaFuncAttributeMaxDynamicSharedMemorySize, DSMEM);

    const int MQ = BATCH * SEQ; // 8192

    // launch 0
    split2_kernel<<<MQ * DMODEL / 4 / 256, 256>>>((const float4*)x, (uint2*)x1, (uint2*)x2, MQ * DMODEL / 4);

    // launch 1
    dim3 gw(DMODEL / 32, DMODEL / 32, 3);
    wtrans_split3_kernel<<<gw, 256>>>(Wq, Wk, Wv,
                                      (__nv_bfloat16*)wqt1, (__nv_bfloat16*)wqt2,
                                      (__nv_bfloat16*)wkt1, (__nv_bfloat16*)wkt2,
                                      (__nv_bfloat16*)wvt1, (__nv_bfloat16*)wvt2);

    // launches 2-4
    dim3 gp(DMODEL / 128, MQ / 128, 1);
    gemm_mma<1, true><<<gp, 256, DSMEM>>>((__nv_bfloat16*)x1, (__nv_bfloat16*)x2, DMODEL, 0,
                                          (__nv_bfloat16*)wqt1, (__nv_bfloat16*)wqt2, DMODEL, 0,
                                          bq, nullptr, (__nv_bfloat16*)q1, (__nv_bfloat16*)q2,
                                          DMODEL, 0, 1.0f, DMODEL);
    gemm_mma<1, true><<<gp, 256, DSMEM>>>((__nv_bfloat16*)x1, (__nv_bfloat16*)x2, DMODEL, 0,
                                          (__nv_bfloat16*)wkt1, (__nv_bfloat16*)wkt2, DMODEL, 0,
                                          bk, nullptr, (__nv_bfloat16*)k1, (__nv_bfloat16*)k2,
                                          DMODEL, 0, 1.0f, DMODEL);
    gemm_mma<2, true><<<gp, 256, DSMEM>>>((__nv_bfloat16*)x1, (__nv_bfloat16*)x2, DMODEL, 0,
                                          (__nv_bfloat16*)wvt1, (__nv_bfloat16*)wvt2, DMODEL, 0,
                                          bv, nullptr, (__nv_bfloat16*)vt1, (__nv_bfloat16*)vt2,
                                          0, 0, 1.0f, DMODEL);

    // launch 5 (ncu -s 5 -c 1 profiles this: the scores GEMM)
    dim3 gs(SEQ / 128, SEQ / 128, BATCH);
    gemm_mma<0, false><<<gs, 256, DSMEM>>>((__nv_bfloat16*)q1, (__nv_bfloat16*)q2, DMODEL, (long long)SEQ * DMODEL,
                                           (__nv_bfloat16*)k1, (__nv_bfloat16*)k2, DMODEL, (long long)SEQ * DMODEL,
                                           nullptr, (float*)s, nullptr, nullptr,
                                           SEQ, (long long)SEQ * SEQ, 0.03125f, DMODEL);

    softmax_planes_kernel<<<BATCH * SEQ, 256>>>((const float*)s, (__nv_bfloat16*)p1, (__nv_bfloat16*)p2);

    dim3 go(DMODEL / 128, SEQ / 128, BATCH);
    gemm_mma<0, false><<<go, 256, DSMEM>>>((__nv_bfloat16*)p1, (__nv_bfloat16*)p2, SEQ, (long long)SEQ * SEQ,
                                           (__nv_bfloat16*)vt1, (__nv_bfloat16*)vt2, SEQ, (long long)DMODEL * SEQ,
                                           nullptr, out, nullptr, nullptr,
                                           DMODEL, (long long)SEQ * DMODEL, 1.0f, SEQ);
}

// round 7
// speedup vs baseline: 1.0470x; 1.0470x over previous
#include <cuda_runtime.h>
#include <cuda_bf16.h>
#include <cstdint>
#include <math.h>

#define BATCH 4
#define SEQ   2048
#define DMODEL 1024

// ---------------- device scratch (fp32, tf32-valued) ----------------
__device__ float g_xr[8388608];                 // rounded x [8192][1024]
__device__ float g_wqt[1048576], g_wkt[1048576], g_wvt[1048576];  // W^T rounded [n][k]
__device__ float g_q[8388608], g_k[8388608];    // q,k rounded [8192][1024]
__device__ float g_vt[8388608];                 // V^T rounded [b][1024][2048]
__device__ float g_s[16777216];                 // scores fp32 [b][2048][2048]
__device__ float g_p[16777216];                 // probs rounded

// ---------------- helpers ----------------
__device__ __forceinline__ uint32_t smem_u32(const void* p) {
    uint32_t a;
    asm("{ .reg .u64 t; cvta.to.shared.u64 t, %1; cvt.u32.u64 %0, t; }" : "=r"(a) : "l"(p));
    return a;
}
__device__ __forceinline__ void cp_async16(uint32_t d, const void* s) {
    asm volatile("cp.async.cg.shared.global [%0], [%1], 16;" :: "r"(d), "l"(s) : "memory");
}
#define CP_COMMIT() asm volatile("cp.async.commit_group;" ::: "memory")
#define CP_WAIT1()  asm volatile("cp.async.wait_group 1;" ::: "memory")
#define CP_WAIT0()  asm volatile("cp.async.wait_group 0;" ::: "memory")

__device__ __forceinline__ void ldsm4(uint32_t* r, uint32_t a) {
    asm volatile("ldmatrix.sync.aligned.m8n8.x4.shared.b16 {%0,%1,%2,%3}, [%4];"
        : "=r"(r[0]), "=r"(r[1]), "=r"(r[2]), "=r"(r[3]) : "r"(a));
}
__device__ __forceinline__ void mma_tf32(float* c, const uint32_t* a, const uint32_t* b) {
    asm volatile("mma.sync.aligned.m16n8k8.row.col.f32.tf32.tf32.f32 "
        "{%0,%1,%2,%3}, {%4,%5,%6,%7}, {%8,%9}, {%0,%1,%2,%3};"
        : "+f"(c[0]), "+f"(c[1]), "+f"(c[2]), "+f"(c[3])
        : "r"(a[0]), "r"(a[1]), "r"(a[2]), "r"(a[3]), "r"(b[0]), "r"(b[1]));
}
// round-to-nearest tf32 (low 13 mantissa bits zeroed, RN)
__device__ __forceinline__ float rna(float x) {
    uint32_t u;
    asm("cvt.rna.tf32.f32 %0, %1;" : "=r"(u) : "f"(x));
    return __uint_as_float(u);
}

// ---------------- prep kernels ----------------
__global__ __launch_bounds__(256) void round_kernel(const float4* __restrict__ X,
                                                    float4* __restrict__ Y, int n4) {
    int i = blockIdx.x * 256 + threadIdx.x;
    if (i >= n4) return;
    float4 v = X[i];
    v.x = rna(v.x); v.y = rna(v.y); v.z = rna(v.z); v.w = rna(v.w);
    Y[i] = v;
}

__global__ __launch_bounds__(256) void wtrans3_kernel(
    const float* __restrict__ Wq, const float* __restrict__ Wk, const float* __restrict__ Wv,
    float* __restrict__ Tq, float* __restrict__ Tk, float* __restrict__ Tv)
{
    const float* W = (blockIdx.z == 0) ? Wq : (blockIdx.z == 1) ? Wk : Wv;
    float* T = (blockIdx.z == 0) ? Tq : (blockIdx.z == 1) ? Tk : Tv;

    __shared__ float t[32][33];
    int k0 = blockIdx.y * 32, n0 = blockIdx.x * 32;
    int tx = threadIdx.x & 31, ty = threadIdx.x >> 5;
    #pragma unroll
    for (int i = 0; i < 4; i++) {
        int k = ty + i * 8;
        t[k][tx] = W[(long long)(k0 + k) * DMODEL + n0 + tx];
    }
    __syncthreads();
    #pragma unroll
    for (int i = 0; i < 4; i++) {
        int n = ty + i * 8;
        T[(long long)(n0 + n) * DMODEL + k0 + tx] = rna(t[tx][n]);
    }
}

// ---------------- GEMM: C = scale*(A·B^T)(+bias); A[M,K], B[N,K] fp32 tf32-valued ----------------
// MODE 0: fp32 C row-major (plain). MODE 1: fp32 C row-major rounded to tf32.
// MODE 2: transposed rounded output (V^T layout).
#define KC 32
#define TROW 144                     // 32 fp32 = 128B + 16B pad (ldmatrix conflict-free)
#define TILE_B (128 * TROW)          // 18432
#define STAGE_B (2 * TILE_B)         // 36864 (A + B tile)
#define DSMEM (2 * STAGE_B)          // 73728

template<int MODE, bool HAS_BIAS>
__global__ __launch_bounds__(256, 2)
void gemm_tf32(const float* __restrict__ A, int ldA, long long sA,
               const float* __restrict__ B, int ldB, long long sB,
               const float* __restrict__ bias,
               float* __restrict__ C, int ldC, long long sC, float scale, int K)
{
    extern __shared__ char smem[];
    const uint32_t sbase = smem_u32(smem);

    const int tid = threadIdx.x, lane = tid & 31, wid = tid >> 5;
    const int wm = wid & 3, wn = wid >> 2;
    const long long z = blockIdx.z;
    A += z * sA; B += z * sB;
    if (MODE != 2) C += z * sC;
    const int m0 = blockIdx.y * 128, n0 = blockIdx.x * 128;

    // ---- load-side addressing: each thread owns one row-half (64B) per tile ----
    const int lrow = tid >> 1;                       // 0..127
    const uint32_t lso = lrow * TROW + (tid & 1) * 64;
    const float* gA = A + (long long)(m0 + lrow) * ldA + (tid & 1) * 16;
    const float* gB = B + (long long)(n0 + lrow) * ldB + (tid & 1) * 16;

    auto load_stage = [&](int stg, int k0) {
        const uint32_t st = sbase + stg * STAGE_B;
        #pragma unroll
        for (int j = 0; j < 4; j++) {
            cp_async16(st + lso + j * 16,          gA + k0 + j * 4);
            cp_async16(st + TILE_B + lso + j * 16, gB + k0 + j * 4);
        }
    };

    // ---- ldmatrix quadrant addressing for tf32 fragments ----
    const uint32_t q8  = ((lane >> 3) & 1) * 8;      // +8 rows for quads 1,3
    const uint32_t qc  = (lane >> 4) * 16;           // +4 fp32 cols for quads 2,3
    const uint32_t arow0 = (wm * 32 + q8 + (lane & 7)) * TROW + qc;
    const uint32_t brow0 = (wn * 64 + q8 + (lane & 7)) * TROW + qc;

    float acc[2][8][4] = {};

    const int CH = K / KC;
    load_stage(0, 0);  CP_COMMIT();
    load_stage(1, KC); CP_COMMIT();

    for (int c = 0; c < CH; c++) {
        if (c + 1 < CH) CP_WAIT1(); else CP_WAIT0();
        __syncthreads();
        const uint32_t st = sbase + (c & 1) * STAGE_B;

        #pragma unroll
        for (int ks = 0; ks < 4; ks++) {
            const uint32_t kb = ks * 32;             // 8 fp32 = 32 bytes per k-step
            uint32_t a[2][4];
            ldsm4(a[0], st + arow0 + kb);
            ldsm4(a[1], st + arow0 + 16 * TROW + kb);
            uint32_t bb[8][2];
            #pragma unroll
            for (int nt2 = 0; nt2 < 4; nt2++) {
                uint32_t r[4];
                ldsm4(r, st + TILE_B + brow0 + nt2 * 16 * TROW + kb);
                bb[nt2 * 2 + 0][0] = r[0]; bb[nt2 * 2 + 0][1] = r[2];
                bb[nt2 * 2 + 1][0] = r[1]; bb[nt2 * 2 + 1][1] = r[3];
            }
            #pragma unroll
            for (int mt = 0; mt < 2; mt++)
                #pragma unroll
                for (int nt = 0; nt < 8; nt++)
                    mma_tf32(acc[mt][nt], a[mt], bb[nt]);
        }
        __syncthreads();
        if (c + 2 < CH) load_stage(c & 1, (c + 2) * KC);
        CP_COMMIT();
    }
    __syncthreads();

    // ---------------- epilogue ----------------
    if (MODE == 2) {
        float* stg = (float*)smem;     // [128][133] fp32 staging (68KB <= 72KB)
        #pragma unroll
        for (int mt = 0; mt < 2; mt++)
            #pragma unroll
            for (int h = 0; h < 2; h++) {
                int m = wm * 32 + mt * 16 + (lane >> 2) + h * 8;
                #pragma unroll
                for (int nt = 0; nt < 8; nt++) {
                    int n = wn * 64 + nt * 8 + ((lane & 3) << 1);
                    float v0 = acc[mt][nt][h * 2 + 0] * scale;
                    float v1 = acc[mt][nt][h * 2 + 1] * scale;
                    if (HAS_BIAS) { v0 += __ldg(bias + n0 + n); v1 += __ldg(bias + n0 + n + 1); }
                    stg[m * 133 + n] = v0;
                    stg[m * 133 + n + 1] = v1;
                }
            }
        __syncthreads();
        #pragma unroll 4
        for (int i = 0; i < 64; i++) {
            int linear = i * 256 + tid;       // 0..16383
            int n = linear >> 7, m = linear & 127;
            float v = stg[m * 133 + n];
            int gm = m0 + m;
            long long idx = ((long long)(gm >> 11) * DMODEL + (n0 + n)) * SEQ + (gm & (SEQ - 1));
            C[idx] = rna(v);
        }
    } else {
        #pragma unroll
        for (int mt = 0; mt < 2; mt++)
            #pragma unroll
            for (int h = 0; h < 2; h++) {
                int m = m0 + wm * 32 + mt * 16 + (lane >> 2) + h * 8;
                #pragma unroll
                for (int nt = 0; nt < 8; nt++) {
                    int n = n0 + wn * 64 + nt * 8 + ((lane & 3) << 1);
                    float v0 = acc[mt][nt][h * 2 + 0] * scale;
                    float v1 = acc[mt][nt][h * 2 + 1] * scale;
                    if (HAS_BIAS) { v0 += __ldg(bias + n); v1 += __ldg(bias + n + 1); }
                    float2 f;
                    if (MODE == 1) { f.x = rna(v0); f.y = rna(v1); }
                    else           { f.x = v0;      f.y = v1; }
                    *(float2*)(C + (long long)m * ldC + n) = f;
                }
            }
    }
}

// ---------------- softmax: fp32 scores -> tf32-rounded probs ----------------
__global__ __launch_bounds__(256) void softmax_kernel(const float* __restrict__ S,
                                                      float* __restrict__ P) {
    const long long row = blockIdx.x;
    const float* p = S + row * SEQ;
    const int tid = threadIdx.x, lane = tid & 31, w = tid >> 5;
    __shared__ float red[8];

    float vals[8];
    const float4 a = *(const float4*)(p + tid * 8);
    const float4 b = *(const float4*)(p + tid * 8 + 4);
    vals[0]=a.x; vals[1]=a.y; vals[2]=a.z; vals[3]=a.w;
    vals[4]=b.x; vals[5]=b.y; vals[6]=b.z; vals[7]=b.w;

    float m = -INFINITY;
    #pragma unroll
    for (int i = 0; i < 8; i++) m = fmaxf(m, vals[i]);
    #pragma unroll
    for (int o = 16; o; o >>= 1) m = fmaxf(m, __shfl_xor_sync(0xffffffffu, m, o));
    if (lane == 0) red[w] = m;
    __syncthreads();
    if (w == 0) {
        float x = red[lane & 7];
        #pragma unroll
        for (int o = 4; o; o >>= 1) x = fmaxf(x, __shfl_xor_sync(0xffffffffu, x, o));
        if (lane == 0) red[0] = x;
    }
    __syncthreads();
    m = red[0];
    __syncthreads();

    float s = 0.0f;
    #pragma unroll
    for (int i = 0; i < 8; i++) { vals[i] = __expf(vals[i] - m); s += vals[i]; }
    #pragma unroll
    for (int o = 16; o; o >>= 1) s += __shfl_xor_sync(0xffffffffu, s, o);
    if (lane == 0) red[w] = s;
    __syncthreads();
    if (w == 0) {
        float x = red[lane & 7];
        #pragma unroll
        for (int o = 4; o; o >>= 1) x += __shfl_xor_sync(0xffffffffu, x, o);
        if (lane == 0) red[0] = x;
    }
    __syncthreads();
    const float inv = 1.0f / red[0];

    float4 o1, o2;
    o1.x = rna(vals[0] * inv); o1.y = rna(vals[1] * inv);
    o1.z = rna(vals[2] * inv); o1.w = rna(vals[3] * inv);
    o2.x = rna(vals[4] * inv); o2.y = rna(vals[5] * inv);
    o2.z = rna(vals[6] * inv); o2.w = rna(vals[7] * inv);
    *(float4*)(P + row * SEQ + tid * 8) = o1;
    *(float4*)(P + row * SEQ + tid * 8 + 4) = o2;
}

// ---------------- launch ----------------
extern "C" void kernel_launch(void* const* d_in, const int* in_sizes, int n_in,
                              void* d_out, int out_size)
{
    const float* x  = (const float*)d_in[0];
    const float* Wq = (const float*)d_in[1];
    const float* bq = (const float*)d_in[2];
    const float* Wk = (const float*)d_in[3];
    const float* bk = (const float*)d_in[4];
    const float* Wv = (const float*)d_in[5];
    const float* bv = (const float*)d_in[6];
    float* out = (float*)d_out;

    void *xr, *wqt, *wkt, *wvt, *q, *k, *vt, *s, *p;
    cudaGetSymbolAddress(&xr, g_xr);
    cudaGetSymbolAddress(&wqt, g_wqt); cudaGetSymbolAddress(&wkt, g_wkt); cudaGetSymbolAddress(&wvt, g_wvt);
    cudaGetSymbolAddress(&q, g_q); cudaGetSymbolAddress(&k, g_k);
    cudaGetSymbolAddress(&vt, g_vt);
    cudaGetSymbolAddress(&s, g_s); cudaGetSymbolAddress(&p, g_p);

    cudaFuncSetAttribute(gemm_tf32<0, false>, cudaFuncAttributeMaxDynamicSharedMemorySize, DSMEM);
    cudaFuncSetAttribute(gemm_tf32<1, true >, cudaFuncAttributeMaxDynamicSharedMemorySize, DSMEM);
    cudaFuncSetAttribute(gemm_tf32<2, true >, cudaFuncAttributeMaxDynamicSharedMemorySize, DSMEM);

    const int MQ = BATCH * SEQ; // 8192

    // launch 0: round x -> tf32 values
    round_kernel<<<MQ * DMODEL / 4 / 256, 256>>>((const float4*)x, (float4*)xr, MQ * DMODEL / 4);

    // launch 1: transpose + round all weights
    dim3 gw(DMODEL / 32, DMODEL / 32, 3);
    wtrans3_kernel<<<gw, 256>>>(Wq, Wk, Wv, (float*)wqt, (float*)wkt, (float*)wvt);

    // launches 2-4: projections
    dim3 gp(DMODEL / 128, MQ / 128, 1);
    gemm_tf32<1, true><<<gp, 256, DSMEM>>>((float*)xr, DMODEL, 0, (float*)wqt, DMODEL, 0,
                                           bq, (float*)q, DMODEL, 0, 1.0f, DMODEL);
    gemm_tf32<1, true><<<gp, 256, DSMEM>>>((float*)xr, DMODEL, 0, (float*)wkt, DMODEL, 0,
                                           bk, (float*)k, DMODEL, 0, 1.0f, DMODEL);
    gemm_tf32<2, true><<<gp, 256, DSMEM>>>((float*)xr, DMODEL, 0, (float*)wvt, DMODEL, 0,
                                           bv, (float*)vt, 0, 0, 1.0f, DMODEL);

    // launch 5 (profiled): scores = Q K^T / 32
    dim3 gs(SEQ / 128, SEQ / 128, BATCH);
    gemm_tf32<0, false><<<gs, 256, DSMEM>>>((float*)q, DMODEL, (long long)SEQ * DMODEL,
                                            (float*)k, DMODEL, (long long)SEQ * DMODEL,
                                            nullptr, (float*)s, SEQ, (long long)SEQ * SEQ,
                                            0.03125f, DMODEL);

    // launch 6: softmax
    softmax_kernel<<<BATCH * SEQ, 256>>>((const float*)s, (float*)p);

    // launch 7: out = P V
    dim3 go(DMODEL / 128, SEQ / 128, BATCH);
    gemm_tf32<0, false><<<go, 256, DSMEM>>>((float*)p, SEQ, (long long)SEQ * SEQ,
                                            (float*)vt, SEQ, (long long)DMODEL * SEQ,
                                            nullptr, out, DMODEL, (long long)SEQ * DMODEL,
                                            1.0f, SEQ);
}

// round 8
// speedup vs baseline: 1.8215x; 1.7398x over previous
#include <cuda_runtime.h>
#include <cuda.h>
#include <cuda_bf16.h>
#include <cstdint>
#include <math.h>

#define BATCH 4
#define SEQ   2048
#define DMODEL 1024

// ---------------- device scratch (fp32, tf32-valued) ----------------
__device__ __align__(128) float g_xr[8388608];                 // rounded x [8192][1024]
__device__ __align__(128) float g_wqt[1048576];
__device__ __align__(128) float g_wkt[1048576];
__device__ __align__(128) float g_wvt[1048576];
__device__ __align__(128) float g_q[8388608];
__device__ __align__(128) float g_k[8388608];
__device__ __align__(128) float g_vt[8388608];                 // V^T [4096][2048]
__device__ __align__(128) float g_s[16777216];                 // scores fp32
__device__ __align__(128) float g_p[16777216];                 // probs rounded

// ---------------- helpers ----------------
__device__ __forceinline__ uint32_t smem_u32(const void* p) {
    uint32_t a;
    asm("{ .reg .u64 t; cvta.to.shared.u64 t, %1; cvt.u32.u64 %0, t; }" : "=r"(a) : "l"(p));
    return a;
}
__device__ __forceinline__ void ldsm4(uint32_t* r, uint32_t a) {
    asm volatile("ldmatrix.sync.aligned.m8n8.x4.shared.b16 {%0,%1,%2,%3}, [%4];"
        : "=r"(r[0]), "=r"(r[1]), "=r"(r[2]), "=r"(r[3]) : "r"(a));
}
__device__ __forceinline__ void mma_tf32(float* c, const uint32_t* a, const uint32_t* b) {
    asm volatile("mma.sync.aligned.m16n8k8.row.col.f32.tf32.tf32.f32 "
        "{%0,%1,%2,%3}, {%4,%5,%6,%7}, {%8,%9}, {%0,%1,%2,%3};"
        : "+f"(c[0]), "+f"(c[1]), "+f"(c[2]), "+f"(c[3])
        : "r"(a[0]), "r"(a[1]), "r"(a[2]), "r"(a[3]), "r"(b[0]), "r"(b[1]));
}
__device__ __forceinline__ float rna(float x) {
    uint32_t u;
    asm("cvt.rna.tf32.f32 %0, %1;" : "=r"(u) : "f"(x));
    return __uint_as_float(u);
}
#define MBAR_INIT(a, c)  asm volatile("mbarrier.init.shared.b64 [%0], %1;" :: "r"(a), "r"(c) : "memory")
#define MBAR_EXPECT(a, b) asm volatile("mbarrier.arrive.expect_tx.shared.b64 _, [%0], %1;" :: "r"(a), "r"(b) : "memory")
#define FENCE_ASYNC()    asm volatile("fence.proxy.async.shared::cta;" ::: "memory")

__device__ __forceinline__ void mbar_wait(uint32_t mbar, uint32_t parity) {
    uint32_t done;
    asm volatile("{\n\t.reg .pred p;\n\t"
        "mbarrier.try_wait.parity.acquire.cta.shared::cta.b64 p, [%1], %2;\n\t"
        "selp.b32 %0, 1, 0, p;\n\t}"
        : "=r"(done) : "r"(mbar), "r"(parity) : "memory");
    while (!done) {
        asm volatile("{\n\t.reg .pred p;\n\t"
            "mbarrier.try_wait.parity.acquire.cta.shared::cta.b64 p, [%1], %2, 0x989680;\n\t"
            "selp.b32 %0, 1, 0, p;\n\t}"
            : "=r"(done) : "r"(mbar), "r"(parity) : "memory");
    }
}
__device__ __forceinline__ void tma2d(uint32_t dst, const CUtensorMap* tm, int x, int y, uint32_t mbar) {
    asm volatile("cp.async.bulk.tensor.2d.shared::cta.global.tile.mbarrier::complete_tx::bytes "
        "[%0], [%1, {%2, %3}], [%4];"
        :: "r"(dst), "l"(tm), "r"(x), "r"(y), "r"(mbar) : "memory");
}

// ---------------- prep kernels ----------------
__global__ __launch_bounds__(256) void round_kernel(const float4* __restrict__ X,
                                                    float4* __restrict__ Y, int n4) {
    int i = blockIdx.x * 256 + threadIdx.x;
    if (i >= n4) return;
    float4 v = X[i];
    v.x = rna(v.x); v.y = rna(v.y); v.z = rna(v.z); v.w = rna(v.w);
    Y[i] = v;
}

__global__ __launch_bounds__(256) void wtrans3_kernel(
    const float* __restrict__ Wq, const float* __restrict__ Wk, const float* __restrict__ Wv,
    float* __restrict__ Tq, float* __restrict__ Tk, float* __restrict__ Tv)
{
    const float* W = (blockIdx.z == 0) ? Wq : (blockIdx.z == 1) ? Wk : Wv;
    float* T = (blockIdx.z == 0) ? Tq : (blockIdx.z == 1) ? Tk : Tv;

    __shared__ float t[32][33];
    int k0 = blockIdx.y * 32, n0 = blockIdx.x * 32;
    int tx = threadIdx.x & 31, ty = threadIdx.x >> 5;
    #pragma unroll
    for (int i = 0; i < 4; i++) {
        int k = ty + i * 8;
        t[k][tx] = W[(long long)(k0 + k) * DMODEL + n0 + tx];
    }
    __syncthreads();
    #pragma unroll
    for (int i = 0; i < 4; i++) {
        int n = ty + i * 8;
        T[(long long)(n0 + n) * DMODEL + k0 + tx] = rna(t[tx][n]);
    }
}

// ---------------- TMA-fed tf32 GEMM: C = scale*(A·B^T)(+bias) ----------------
// Tiles 128x128, KC=32 fp32 (=128B rows), SW128 swizzled smem, 3-stage mbarrier pipe.
#define KC 32
#define TILE_B 16384                  // 128 rows x 128 B
#define STAGE_B (2 * TILE_B)          // A + B
#define NSTAGE 3
#define DSMEM (1024 + NSTAGE * STAGE_B + 64)   // 99392

template<int MODE, bool HAS_BIAS>
__global__ __launch_bounds__(256, 2)
void gemm_tma(const __grid_constant__ CUtensorMap tmA,
              const __grid_constant__ CUtensorMap tmB,
              const float* __restrict__ bias,
              float* __restrict__ C, int ldC, long long sC,
              float scale, int K, int mBatchRows, int nBatchRows)
{
    extern __shared__ char smem[];
    const uint32_t sbase = smem_u32(smem);
    const uint32_t tiles = (sbase + 1023) & ~1023u;
    const uint32_t ctrl  = tiles + NSTAGE * STAGE_B;

    const int tid = threadIdx.x, lane = tid & 31, wid = tid >> 5;
    const int wm = wid & 3, wn = wid >> 2;
    const int z = blockIdx.z;
    if (MODE != 2) C += (long long)z * sC;
    const int m0 = blockIdx.y * 128, n0 = blockIdx.x * 128;
    const int mrow0 = m0 + z * mBatchRows;
    const int nrow0 = n0 + z * nBatchRows;

    if (tid == 0) {
        #pragma unroll
        for (int s = 0; s < NSTAGE; s++) MBAR_INIT(ctrl + s * 8, 1);
        FENCE_ASYNC();
    }
    __syncthreads();

    const int CH = K / KC;

    // producer prologue (single thread)
    if (tid == 0) {
        #pragma unroll
        for (int s = 0; s < NSTAGE; s++) {
            if (s < CH) {
                MBAR_EXPECT(ctrl + s * 8, 2 * TILE_B);
                tma2d(tiles + s * STAGE_B,          &tmA, s * KC, mrow0, ctrl + s * 8);
                tma2d(tiles + s * STAGE_B + TILE_B, &tmB, s * KC, nrow0, ctrl + s * 8);
            }
        }
    }

    // ---- consumer fragment addressing (swizzled) ----
    const uint32_t xc = (lane & 7) << 4;                 // swizzle XOR for this thread's rows
    const uint32_t q8 = ((lane >> 3) & 1) << 3;
    const uint32_t qc = (lane >> 4) << 4;                // 0 or 16 bytes
    uint32_t aoff[2], boff[4];
    #pragma unroll
    for (int mt = 0; mt < 2; mt++)
        aoff[mt] = (wm * 32 + mt * 16 + q8 + (lane & 7)) * 128;
    #pragma unroll
    for (int nt2 = 0; nt2 < 4; nt2++)
        boff[nt2] = (wn * 64 + nt2 * 16 + q8 + (lane & 7)) * 128;

    float acc[2][8][4] = {};

    int stage = 0, phase = 0;
    for (int c = 0; c < CH; c++) {
        mbar_wait(ctrl + stage * 8, phase);
        const uint32_t stA = tiles + stage * STAGE_B;
        const uint32_t stB = stA + TILE_B;

        #pragma unroll
        for (int ks = 0; ks < 4; ks++) {
            const uint32_t kb = (qc + ks * 32) ^ xc;
            uint32_t a[2][4];
            ldsm4(a[0], stA + aoff[0] + kb);
            ldsm4(a[1], stA + aoff[1] + kb);
            uint32_t bb[8][2];
            #pragma unroll
            for (int nt2 = 0; nt2 < 4; nt2++) {
                uint32_t r[4];
                ldsm4(r, stB + boff[nt2] + kb);
                bb[nt2 * 2 + 0][0] = r[0]; bb[nt2 * 2 + 0][1] = r[2];
                bb[nt2 * 2 + 1][0] = r[1]; bb[nt2 * 2 + 1][1] = r[3];
            }
            #pragma unroll
            for (int mt = 0; mt < 2; mt++)
                #pragma unroll
                for (int nt = 0; nt < 8; nt++)
                    mma_tf32(acc[mt][nt], a[mt], bb[nt]);
        }
        __syncthreads();
        if (tid == 0 && c + NSTAGE < CH) {
            const int cn = c + NSTAGE;
            MBAR_EXPECT(ctrl + stage * 8, 2 * TILE_B);
            tma2d(tiles + stage * STAGE_B,          &tmA, cn * KC, mrow0, ctrl + stage * 8);
            tma2d(tiles + stage * STAGE_B + TILE_B, &tmB, cn * KC, nrow0, ctrl + stage * 8);
        }
        if (++stage == NSTAGE) { stage = 0; phase ^= 1; }
    }
    __syncthreads();

    // ---------------- epilogue ----------------
    if (MODE == 2) {
        float* stg = (float*)smem;     // [128][133] fp32 staging
        #pragma unroll
        for (int mt = 0; mt < 2; mt++)
            #pragma unroll
            for (int h = 0; h < 2; h++) {
                int m = wm * 32 + mt * 16 + (lane >> 2) + h * 8;
                #pragma unroll
                for (int nt = 0; nt < 8; nt++) {
                    int n = wn * 64 + nt * 8 + ((lane & 3) << 1);
                    float v0 = acc[mt][nt][h * 2 + 0] * scale;
                    float v1 = acc[mt][nt][h * 2 + 1] * scale;
                    if (HAS_BIAS) { v0 += __ldg(bias + n0 + n); v1 += __ldg(bias + n0 + n + 1); }
                    stg[m * 133 + n] = v0;
                    stg[m * 133 + n + 1] = v1;
                }
            }
        __syncthreads();
        #pragma unroll 4
        for (int i = 0; i < 64; i++) {
            int linear = i * 256 + tid;
            int n = linear >> 7, m = linear & 127;
            float v = stg[m * 133 + n];
            int gm = m0 + m;
            long long idx = ((long long)(gm >> 11) * DMODEL + (n0 + n)) * SEQ + (gm & (SEQ - 1));
            C[idx] = rna(v);
        }
    } else {
        #pragma unroll
        for (int mt = 0; mt < 2; mt++)
            #pragma unroll
            for (int h = 0; h < 2; h++) {
                int m = m0 + wm * 32 + mt * 16 + (lane >> 2) + h * 8;
                #pragma unroll
                for (int nt = 0; nt < 8; nt++) {
                    int n = n0 + wn * 64 + nt * 8 + ((lane & 3) << 1);
                    float v0 = acc[mt][nt][h * 2 + 0] * scale;
                    float v1 = acc[mt][nt][h * 2 + 1] * scale;
                    if (HAS_BIAS) { v0 += __ldg(bias + n); v1 += __ldg(bias + n + 1); }
                    float2 f;
                    if (MODE == 1) { f.x = rna(v0); f.y = rna(v1); }
                    else           { f.x = v0;      f.y = v1; }
                    *(float2*)(C + (long long)m * ldC + n) = f;
                }
            }
    }
}

// ---------------- softmax: fp32 scores -> tf32-rounded probs ----------------
__global__ __launch_bounds__(256) void softmax_kernel(const float* __restrict__ S,
                                                      float* __restrict__ P) {
    const long long row = blockIdx.x;
    const float* p = S + row * SEQ;
    const int tid = threadIdx.x, lane = tid & 31, w = tid >> 5;
    __shared__ float red[8];

    float vals[8];
    const float4 a = *(const float4*)(p + tid * 8);
    const float4 b = *(const float4*)(p + tid * 8 + 4);
    vals[0]=a.x; vals[1]=a.y; vals[2]=a.z; vals[3]=a.w;
    vals[4]=b.x; vals[5]=b.y; vals[6]=b.z; vals[7]=b.w;

    float m = -INFINITY;
    #pragma unroll
    for (int i = 0; i < 8; i++) m = fmaxf(m, vals[i]);
    #pragma unroll
    for (int o = 16; o; o >>= 1) m = fmaxf(m, __shfl_xor_sync(0xffffffffu, m, o));
    if (lane == 0) red[w] = m;
    __syncthreads();
    if (w == 0) {
        float x = red[lane & 7];
        #pragma unroll
        for (int o = 4; o; o >>= 1) x = fmaxf(x, __shfl_xor_sync(0xffffffffu, x, o));
        if (lane == 0) red[0] = x;
    }
    __syncthreads();
    m = red[0];
    __syncthreads();

    float s = 0.0f;
    #pragma unroll
    for (int i = 0; i < 8; i++) { vals[i] = __expf(vals[i] - m); s += vals[i]; }
    #pragma unroll
    for (int o = 16; o; o >>= 1) s += __shfl_xor_sync(0xffffffffu, s, o);
    if (lane == 0) red[w] = s;
    __syncthreads();
    if (w == 0) {
        float x = red[lane & 7];
        #pragma unroll
        for (int o = 4; o; o >>= 1) x += __shfl_xor_sync(0xffffffffu, x, o);
        if (lane == 0) red[0] = x;
    }
    __syncthreads();
    const float inv = 1.0f / red[0];

    float4 o1, o2;
    o1.x = rna(vals[0] * inv); o1.y = rna(vals[1] * inv);
    o1.z = rna(vals[2] * inv); o1.w = rna(vals[3] * inv);
    o2.x = rna(vals[4] * inv); o2.y = rna(vals[5] * inv);
    o2.z = rna(vals[6] * inv); o2.w = rna(vals[7] * inv);
    *(float4*)(P + row * SEQ + tid * 8) = o1;
    *(float4*)(P + row * SEQ + tid * 8 + 4) = o2;
}

// ---------------- host: tensormap encode via driver entry point ----------------
typedef CUresult (*EncodeFn)(CUtensorMap*, CUtensorMapDataType, cuuint32_t, void*,
                             const cuuint64_t*, const cuuint64_t*, const cuuint32_t*,
                             const cuuint32_t*, CUtensorMapInterleave, CUtensorMapSwizzle,
                             CUtensorMapL2promotion, CUtensorMapFloatOOBfill);

static void make2d(EncodeFn enc, CUtensorMap* m, void* p, unsigned long long rows, unsigned long long cols) {
    cuuint64_t dims[2]    = {cols, rows};
    cuuint64_t strides[1] = {cols * 4};
    cuuint32_t box[2]     = {32, 128};
    cuuint32_t es[2]      = {1, 1};
    enc(m, CU_TENSOR_MAP_DATA_TYPE_FLOAT32, 2, p, dims, strides, box, es,
        CU_TENSOR_MAP_INTERLEAVE_NONE, CU_TENSOR_MAP_SWIZZLE_128B,
        CU_TENSOR_MAP_L2_PROMOTION_L2_128B, CU_TENSOR_MAP_FLOAT_OOB_FILL_NONE);
}

// ---------------- launch ----------------
extern "C" void kernel_launch(void* const* d_in, const int* in_sizes, int n_in,
                              void* d_out, int out_size)
{
    const float* x  = (const float*)d_in[0];
    const float* Wq = (const float*)d_in[1];
    const float* bq = (const float*)d_in[2];
    const float* Wk = (const float*)d_in[3];
    const float* bk = (const float*)d_in[4];
    const float* Wv = (const float*)d_in[5];
    const float* bv = (const float*)d_in[6];
    float* out = (float*)d_out;

    void *xr, *wqt, *wkt, *wvt, *q, *k, *vt, *s, *p;
    cudaGetSymbolAddress(&xr, g_xr);
    cudaGetSymbolAddress(&wqt, g_wqt); cudaGetSymbolAddress(&wkt, g_wkt); cudaGetSymbolAddress(&wvt, g_wvt);
    cudaGetSymbolAddress(&q, g_q); cudaGetSymbolAddress(&k, g_k);
    cudaGetSymbolAddress(&vt, g_vt);
    cudaGetSymbolAddress(&s, g_s); cudaGetSymbolAddress(&p, g_p);

    // tensormap encoder (driver API via runtime entry point; no -lcuda link)
    EncodeFn enc = nullptr;
    {
        void* fp = nullptr;
        cudaDriverEntryPointQueryResult qr;
        cudaGetDriverEntryPointByVersion("cuTensorMapEncodeTiled", &fp, 12000,
                                         cudaEnableDefault, &qr);
        enc = (EncodeFn)fp;
    }
    CUtensorMap tm_x, tm_wq, tm_wk, tm_wv, tm_q, tm_k, tm_p, tm_vt;
    make2d(enc, &tm_x,  xr,  8192, 1024);
    make2d(enc, &tm_wq, wqt, 1024, 1024);
    make2d(enc, &tm_wk, wkt, 1024, 1024);
    make2d(enc, &tm_wv, wvt, 1024, 1024);
    make2d(enc, &tm_q,  q,   8192, 1024);
    make2d(enc, &tm_k,  k,   8192, 1024);
    make2d(enc, &tm_p,  p,   8192, 2048);
    make2d(enc, &tm_vt, vt,  4096, 2048);

    cudaFuncSetAttribute(gemm_tma<0, false>, cudaFuncAttributeMaxDynamicSharedMemorySize, DSMEM);
    cudaFuncSetAttribute(gemm_tma<1, true >, cudaFuncAttributeMaxDynamicSharedMemorySize, DSMEM);
    cudaFuncSetAttribute(gemm_tma<2, true >, cudaFuncAttributeMaxDynamicSharedMemorySize, DSMEM);

    const int MQ = BATCH * SEQ; // 8192

    // launch 0: round x -> tf32 values
    round_kernel<<<MQ * DMODEL / 4 / 256, 256>>>((const float4*)x, (float4*)xr, MQ * DMODEL / 4);

    // launch 1: transpose + round all weights
    dim3 gw(DMODEL / 32, DMODEL / 32, 3);
    wtrans3_kernel<<<gw, 256>>>(Wq, Wk, Wv, (float*)wqt, (float*)wkt, (float*)wvt);

    // launches 2-4: projections (M=8192, N=1024, K=1024)
    dim3 gp(DMODEL / 128, MQ / 128, 1);
    gemm_tma<1, true><<<gp, 256, DSMEM>>>(tm_x, tm_wq, bq, (float*)q, DMODEL, 0, 1.0f, DMODEL, 0, 0);
    gemm_tma<1, true><<<gp, 256, DSMEM>>>(tm_x, tm_wk, bk, (float*)k, DMODEL, 0, 1.0f, DMODEL, 0, 0);
    gemm_tma<2, true><<<gp, 256, DSMEM>>>(tm_x, tm_wv, bv, (float*)vt, 0, 0, 1.0f, DMODEL, 0, 0);

    // launch 5 (profiled): scores = Q K^T / 32, batched over z
    dim3 gs(SEQ / 128, SEQ / 128, BATCH);
    gemm_tma<0, false><<<gs, 256, DSMEM>>>(tm_q, tm_k, nullptr, (float*)s, SEQ,
                                           (long long)SEQ * SEQ, 0.03125f, DMODEL, SEQ, SEQ);

    // launch 6: softmax
    softmax_kernel<<<BATCH * SEQ, 256>>>((const float*)s, (float*)p);

    // launch 7: out = P V
    dim3 go(DMODEL / 128, SEQ / 128, BATCH);
    gemm_tma<0, false><<<go, 256, DSMEM>>>(tm_p, tm_vt, nullptr, out, DMODEL,
                                           (long long)SEQ * DMODEL, 1.0f, SEQ, SEQ, DMODEL);
}

// round 9
// speedup vs baseline: 1.9368x; 1.0633x over previous
#include <cuda_runtime.h>
#include <cuda.h>
#include <cuda_bf16.h>
#include <cstdint>
#include <math.h>

#define BATCH 4
#define SEQ   2048
#define DMODEL 1024

// ---------------- device scratch (fp32, tf32-valued) ----------------
__device__ __align__(128) float g_xr[8388608];                 // rounded x [8192][1024]
__device__ __align__(128) float g_wqt[1048576];
__device__ __align__(128) float g_wkt[1048576];
__device__ __align__(128) float g_wvt[1048576];
__device__ __align__(128) float g_q[8388608];
__device__ __align__(128) float g_k[8388608];
__device__ __align__(128) float g_vt[8388608];                 // V^T [4096][2048]
__device__ __align__(128) float g_s[16777216];                 // scores fp32
__device__ __align__(128) float g_p[16777216];                 // probs rounded

// ---------------- helpers ----------------
__device__ __forceinline__ uint32_t smem_u32(const void* p) {
    uint32_t a;
    asm("{ .reg .u64 t; cvta.to.shared.u64 t, %1; cvt.u32.u64 %0, t; }" : "=r"(a) : "l"(p));
    return a;
}
__device__ __forceinline__ void ldsm4(uint32_t* r, uint32_t a) {
    asm volatile("ldmatrix.sync.aligned.m8n8.x4.shared.b16 {%0,%1,%2,%3}, [%4];"
        : "=r"(r[0]), "=r"(r[1]), "=r"(r[2]), "=r"(r[3]) : "r"(a));
}
__device__ __forceinline__ void mma_tf32(float* c, const uint32_t* a, const uint32_t* b) {
    asm volatile("mma.sync.aligned.m16n8k8.row.col.f32.tf32.tf32.f32 "
        "{%0,%1,%2,%3}, {%4,%5,%6,%7}, {%8,%9}, {%0,%1,%2,%3};"
        : "+f"(c[0]), "+f"(c[1]), "+f"(c[2]), "+f"(c[3])
        : "r"(a[0]), "r"(a[1]), "r"(a[2]), "r"(a[3]), "r"(b[0]), "r"(b[1]));
}
__device__ __forceinline__ float rna(float x) {
    uint32_t u;
    asm("cvt.rna.tf32.f32 %0, %1;" : "=r"(u) : "f"(x));
    return __uint_as_float(u);
}
#define MBAR_INIT(a, c)  asm volatile("mbarrier.init.shared.b64 [%0], %1;" :: "r"(a), "r"(c) : "memory")
#define MBAR_EXPECT(a, b) asm volatile("mbarrier.arrive.expect_tx.shared.b64 _, [%0], %1;" :: "r"(a), "r"(b) : "memory")
#define FENCE_ASYNC()    asm volatile("fence.proxy.async.shared::cta;" ::: "memory")

__device__ __forceinline__ void mbar_wait(uint32_t mbar, uint32_t parity) {
    uint32_t done;
    asm volatile("{\n\t.reg .pred p;\n\t"
        "mbarrier.try_wait.parity.acquire.cta.shared::cta.b64 p, [%1], %2;\n\t"
        "selp.b32 %0, 1, 0, p;\n\t}"
        : "=r"(done) : "r"(mbar), "r"(parity) : "memory");
    while (!done) {
        asm volatile("{\n\t.reg .pred p;\n\t"
            "mbarrier.try_wait.parity.acquire.cta.shared::cta.b64 p, [%1], %2, 0x989680;\n\t"
            "selp.b32 %0, 1, 0, p;\n\t}"
            : "=r"(done) : "r"(mbar), "r"(parity) : "memory");
    }
}
__device__ __forceinline__ void tma2d(uint32_t dst, const CUtensorMap* tm, int x, int y, uint32_t mbar) {
    asm volatile("cp.async.bulk.tensor.2d.shared::cta.global.tile.mbarrier::complete_tx::bytes "
        "[%0], [%1, {%2, %3}], [%4];"
        :: "r"(dst), "l"(tm), "r"(x), "r"(y), "r"(mbar) : "memory");
}

// ---------------- prep kernels ----------------
__global__ __launch_bounds__(256) void round_kernel(const float4* __restrict__ X,
                                                    float4* __restrict__ Y, int n4) {
    int i = blockIdx.x * 256 + threadIdx.x;
    if (i >= n4) return;
    float4 v = X[i];
    v.x = rna(v.x); v.y = rna(v.y); v.z = rna(v.z); v.w = rna(v.w);
    Y[i] = v;
}

__global__ __launch_bounds__(256) void wtrans3_kernel(
    const float* __restrict__ Wq, const float* __restrict__ Wk, const float* __restrict__ Wv,
    float* __restrict__ Tq, float* __restrict__ Tk, float* __restrict__ Tv)
{
    const float* W = (blockIdx.z == 0) ? Wq : (blockIdx.z == 1) ? Wk : Wv;
    float* T = (blockIdx.z == 0) ? Tq : (blockIdx.z == 1) ? Tk : Tv;

    __shared__ float t[32][33];
    int k0 = blockIdx.y * 32, n0 = blockIdx.x * 32;
    int tx = threadIdx.x & 31, ty = threadIdx.x >> 5;
    #pragma unroll
    for (int i = 0; i < 4; i++) {
        int k = ty + i * 8;
        t[k][tx] = W[(long long)(k0 + k) * DMODEL + n0 + tx];
    }
    __syncthreads();
    #pragma unroll
    for (int i = 0; i < 4; i++) {
        int n = ty + i * 8;
        T[(long long)(n0 + n) * DMODEL + k0 + tx] = rna(t[tx][n]);
    }
}

// ---------------- shared GEMM plumbing ----------------
#define KC 32
#define TILE_B 16384                  // 128 rows x 128 B
#define STAGE_B (2 * TILE_B)          // A + B
#define NSTAGE 3
#define DSMEM (1024 + NSTAGE * STAGE_B + 64)

// mainloop: fills acc[2][8][4]; interleaved ldsm/MMA
#define GEMM_MAINLOOP(tmAp, tmBp, mrow0, nrow0)                                           \
    if (tid == 0) {                                                                       \
        _Pragma("unroll")                                                                 \
        for (int s = 0; s < NSTAGE; s++) MBAR_INIT(ctrl + s * 8, 1);                      \
        FENCE_ASYNC();                                                                    \
    }                                                                                     \
    __syncthreads();                                                                      \
    if (tid == 0) {                                                                       \
        _Pragma("unroll")                                                                 \
        for (int s = 0; s < NSTAGE; s++) {                                                \
            if (s < CH) {                                                                 \
                MBAR_EXPECT(ctrl + s * 8, 2 * TILE_B);                                    \
                tma2d(tiles + s * STAGE_B,          tmAp, s * KC, (mrow0), ctrl + s * 8); \
                tma2d(tiles + s * STAGE_B + TILE_B, tmBp, s * KC, (nrow0), ctrl + s * 8); \
            }                                                                             \
        }                                                                                 \
    }                                                                                     \
    {                                                                                     \
        int stage = 0, phase = 0;                                                         \
        for (int c = 0; c < CH; c++) {                                                    \
            mbar_wait(ctrl + stage * 8, phase);                                           \
            const uint32_t stA = tiles + stage * STAGE_B;                                 \
            const uint32_t stB = stA + TILE_B;                                            \
            _Pragma("unroll")                                                             \
            for (int ks = 0; ks < 4; ks++) {                                              \
                const uint32_t kb = (qc + ks * 32) ^ xc;                                  \
                uint32_t a[2][4];                                                         \
                ldsm4(a[0], stA + aoff[0] + kb);                                          \
                ldsm4(a[1], stA + aoff[1] + kb);                                          \
                uint32_t bb[4][2];                                                        \
                {                                                                         \
                    uint32_t r[4];                                                        \
                    ldsm4(r, stB + boff[0] + kb);                                         \
                    bb[0][0] = r[0]; bb[0][1] = r[2];                                     \
                    bb[1][0] = r[1]; bb[1][1] = r[3];                                     \
                    ldsm4(r, stB + boff[1] + kb);                                         \
                    bb[2][0] = r[0]; bb[2][1] = r[2];                                     \
                    bb[3][0] = r[1]; bb[3][1] = r[3];                                     \
                }                                                                         \
                _Pragma("unroll")                                                         \
                for (int nt = 0; nt < 4; nt++) {                                          \
                    mma_tf32(acc[0][nt], a[0], bb[nt]);                                   \
                    mma_tf32(acc[1][nt], a[1], bb[nt]);                                   \
                }                                                                         \
                {                                                                         \
                    uint32_t r[4];                                                        \
                    ldsm4(r, stB + boff[2] + kb);                                         \
                    bb[0][0] = r[0]; bb[0][1] = r[2];                                     \
                    bb[1][0] = r[1]; bb[1][1] = r[3];                                     \
                    ldsm4(r, stB + boff[3] + kb);                                         \
                    bb[2][0] = r[0]; bb[2][1] = r[2];                                     \
                    bb[3][0] = r[1]; bb[3][1] = r[3];                                     \
                }                                                                         \
                _Pragma("unroll")                                                         \
                for (int nt = 0; nt < 4; nt++) {                                          \
                    mma_tf32(acc[0][4 + nt], a[0], bb[nt]);                               \
                    mma_tf32(acc[1][4 + nt], a[1], bb[nt]);                               \
                }                                                                         \
            }                                                                             \
            __syncthreads();                                                              \
            if (tid == 0 && c + NSTAGE < CH) {                                            \
                const int cn = c + NSTAGE;                                                \
                MBAR_EXPECT(ctrl + stage * 8, 2 * TILE_B);                                \
                tma2d(tiles + stage * STAGE_B,          tmAp, cn * KC, (mrow0), ctrl + stage * 8); \
                tma2d(tiles + stage * STAGE_B + TILE_B, tmBp, cn * KC, (nrow0), ctrl + stage * 8); \
            }                                                                             \
            if (++stage == NSTAGE) { stage = 0; phase ^= 1; }                             \
        }                                                                                 \
    }                                                                                     \
    __syncthreads();

// ---------------- merged QKV projection (z selects q/k/v) ----------------
__global__ __launch_bounds__(256, 2)
void proj_qkv(const __grid_constant__ CUtensorMap tmX,
              const __grid_constant__ CUtensorMap tmWq,
              const __grid_constant__ CUtensorMap tmWk,
              const __grid_constant__ CUtensorMap tmWv,
              const float* __restrict__ bq, const float* __restrict__ bk, const float* __restrict__ bv,
              float* __restrict__ Q, float* __restrict__ Kmat, float* __restrict__ VT)
{
    extern __shared__ char smem[];
    const uint32_t sbase = smem_u32(smem);
    const uint32_t tiles = (sbase + 1023) & ~1023u;
    const uint32_t ctrl  = tiles + NSTAGE * STAGE_B;

    const int tid = threadIdx.x, lane = tid & 31, wid = tid >> 5;
    const int wm = wid & 3, wn = wid >> 2;
    const int z = blockIdx.z;
    const int m0 = blockIdx.y * 128, n0 = blockIdx.x * 128;

    const CUtensorMap* tb = (z == 0) ? &tmWq : (z == 1) ? &tmWk : &tmWv;
    const float* bias = (z == 0) ? bq : (z == 1) ? bk : bv;

    const uint32_t xc = (lane & 7) << 4;
    const uint32_t q8 = ((lane >> 3) & 1) << 3;
    const uint32_t qc = (lane >> 4) << 4;
    uint32_t aoff[2], boff[4];
    #pragma unroll
    for (int mt = 0; mt < 2; mt++)
        aoff[mt] = (wm * 32 + mt * 16 + q8 + (lane & 7)) * 128;
    #pragma unroll
    for (int nt2 = 0; nt2 < 4; nt2++)
        boff[nt2] = (wn * 64 + nt2 * 16 + q8 + (lane & 7)) * 128;

    float acc[2][8][4] = {};
    const int CH = DMODEL / KC;

    GEMM_MAINLOOP(&tmX, tb, m0, n0)

    if (z == 2) {
        // V: transposed output (V^T layout [1024][2048] per batch, batches stacked)
        float* stg = (float*)smem;
        #pragma unroll
        for (int mt = 0; mt < 2; mt++)
            #pragma unroll
            for (int h = 0; h < 2; h++) {
                int m = wm * 32 + mt * 16 + (lane >> 2) + h * 8;
                #pragma unroll
                for (int nt = 0; nt < 8; nt++) {
                    int n = wn * 64 + nt * 8 + ((lane & 3) << 1);
                    float v0 = acc[mt][nt][h * 2 + 0] + __ldg(bias + n0 + n);
                    float v1 = acc[mt][nt][h * 2 + 1] + __ldg(bias + n0 + n + 1);
                    stg[m * 133 + n] = v0;
                    stg[m * 133 + n + 1] = v1;
                }
            }
        __syncthreads();
        #pragma unroll 4
        for (int i = 0; i < 64; i++) {
            int linear = i * 256 + tid;
            int n = linear >> 7, m = linear & 127;
            float v = stg[m * 133 + n];
            int gm = m0 + m;
            long long idx = ((long long)(gm >> 11) * DMODEL + (n0 + n)) * SEQ + (gm & (SEQ - 1));
            VT[idx] = rna(v);
        }
    } else {
        float* C = (z == 0) ? Q : Kmat;
        #pragma unroll
        for (int mt = 0; mt < 2; mt++)
            #pragma unroll
            for (int h = 0; h < 2; h++) {
                int m = m0 + wm * 32 + mt * 16 + (lane >> 2) + h * 8;
                #pragma unroll
                for (int nt = 0; nt < 8; nt++) {
                    int n = n0 + wn * 64 + nt * 8 + ((lane & 3) << 1);
                    float v0 = acc[mt][nt][h * 2 + 0] + __ldg(bias + n);
                    float v1 = acc[mt][nt][h * 2 + 1] + __ldg(bias + n + 1);
                    float2 f; f.x = rna(v0); f.y = rna(v1);
                    *(float2*)(C + (long long)m * DMODEL + n) = f;
                }
            }
    }
}

// ---------------- generic TMA GEMM (scores / PV): C = scale*(A·B^T) ----------------
__global__ __launch_bounds__(256, 2)
void gemm_tma(const __grid_constant__ CUtensorMap tmA,
              const __grid_constant__ CUtensorMap tmB,
              float* __restrict__ C, int ldC, long long sC,
              float scale, int K, int mBatchRows, int nBatchRows)
{
    extern __shared__ char smem[];
    const uint32_t sbase = smem_u32(smem);
    const uint32_t tiles = (sbase + 1023) & ~1023u;
    const uint32_t ctrl  = tiles + NSTAGE * STAGE_B;

    const int tid = threadIdx.x, lane = tid & 31, wid = tid >> 5;
    const int wm = wid & 3, wn = wid >> 2;
    const int z = blockIdx.z;
    C += (long long)z * sC;
    const int m0 = blockIdx.y * 128, n0 = blockIdx.x * 128;
    const int mrow0 = m0 + z * mBatchRows;
    const int nrow0 = n0 + z * nBatchRows;

    const uint32_t xc = (lane & 7) << 4;
    const uint32_t q8 = ((lane >> 3) & 1) << 3;
    const uint32_t qc = (lane >> 4) << 4;
    uint32_t aoff[2], boff[4];
    #pragma unroll
    for (int mt = 0; mt < 2; mt++)
        aoff[mt] = (wm * 32 + mt * 16 + q8 + (lane & 7)) * 128;
    #pragma unroll
    for (int nt2 = 0; nt2 < 4; nt2++)
        boff[nt2] = (wn * 64 + nt2 * 16 + q8 + (lane & 7)) * 128;

    float acc[2][8][4] = {};
    const int CH = K / KC;

    GEMM_MAINLOOP(&tmA, &tmB, mrow0, nrow0)

    #pragma unroll
    for (int mt = 0; mt < 2; mt++)
        #pragma unroll
        for (int h = 0; h < 2; h++) {
            int m = m0 + wm * 32 + mt * 16 + (lane >> 2) + h * 8;
            #pragma unroll
            for (int nt = 0; nt < 8; nt++) {
                int n = n0 + wn * 64 + nt * 8 + ((lane & 3) << 1);
                float2 f;
                f.x = acc[mt][nt][h * 2 + 0] * scale;
                f.y = acc[mt][nt][h * 2 + 1] * scale;
                *(float2*)(C + (long long)m * ldC + n) = f;
            }
        }
}

// ---------------- softmax: fp32 scores -> tf32-rounded probs ----------------
__global__ __launch_bounds__(256) void softmax_kernel(const float* __restrict__ S,
                                                      float* __restrict__ P) {
    const long long row = blockIdx.x;
    const float* p = S + row * SEQ;
    const int tid = threadIdx.x, lane = tid & 31, w = tid >> 5;
    __shared__ float red[8];

    float vals[8];
    const float4 a = *(const float4*)(p + tid * 8);
    const float4 b = *(const float4*)(p + tid * 8 + 4);
    vals[0]=a.x; vals[1]=a.y; vals[2]=a.z; vals[3]=a.w;
    vals[4]=b.x; vals[5]=b.y; vals[6]=b.z; vals[7]=b.w;

    float m = -INFINITY;
    #pragma unroll
    for (int i = 0; i < 8; i++) m = fmaxf(m, vals[i]);
    #pragma unroll
    for (int o = 16; o; o >>= 1) m = fmaxf(m, __shfl_xor_sync(0xffffffffu, m, o));
    if (lane == 0) red[w] = m;
    __syncthreads();
    if (w == 0) {
        float x = red[lane & 7];
        #pragma unroll
        for (int o = 4; o; o >>= 1) x = fmaxf(x, __shfl_xor_sync(0xffffffffu, x, o));
        if (lane == 0) red[0] = x;
    }
    __syncthreads();
    m = red[0];
    __syncthreads();

    float s = 0.0f;
    #pragma unroll
    for (int i = 0; i < 8; i++) { vals[i] = __expf(vals[i] - m); s += vals[i]; }
    #pragma unroll
    for (int o = 16; o; o >>= 1) s += __shfl_xor_sync(0xffffffffu, s, o);
    if (lane == 0) red[w] = s;
    __syncthreads();
    if (w == 0) {
        float x = red[lane & 7];
        #pragma unroll
        for (int o = 4; o; o >>= 1) x += __shfl_xor_sync(0xffffffffu, x, o);
        if (lane == 0) red[0] = x;
    }
    __syncthreads();
    const float inv = 1.0f / red[0];

    float4 o1, o2;
    o1.x = rna(vals[0] * inv); o1.y = rna(vals[1] * inv);
    o1.z = rna(vals[2] * inv); o1.w = rna(vals[3] * inv);
    o2.x = rna(vals[4] * inv); o2.y = rna(vals[5] * inv);
    o2.z = rna(vals[6] * inv); o2.w = rna(vals[7] * inv);
    *(float4*)(P + row * SEQ + tid * 8) = o1;
    *(float4*)(P + row * SEQ + tid * 8 + 4) = o2;
}

// ---------------- host: tensormap encode via driver entry point ----------------
typedef CUresult (*EncodeFn)(CUtensorMap*, CUtensorMapDataType, cuuint32_t, void*,
                             const cuuint64_t*, const cuuint64_t*, const cuuint32_t*,
                             const cuuint32_t*, CUtensorMapInterleave, CUtensorMapSwizzle,
                             CUtensorMapL2promotion, CUtensorMapFloatOOBfill);

static void make2d(EncodeFn enc, CUtensorMap* m, void* p, unsigned long long rows, unsigned long long cols) {
    cuuint64_t dims[2]    = {cols, rows};
    cuuint64_t strides[1] = {cols * 4};
    cuuint32_t box[2]     = {32, 128};
    cuuint32_t es[2]      = {1, 1};
    enc(m, CU_TENSOR_MAP_DATA_TYPE_FLOAT32, 2, p, dims, strides, box, es,
        CU_TENSOR_MAP_INTERLEAVE_NONE, CU_TENSOR_MAP_SWIZZLE_128B,
        CU_TENSOR_MAP_L2_PROMOTION_L2_128B, CU_TENSOR_MAP_FLOAT_OOB_FILL_NONE);
}

// ---------------- launch ----------------
extern "C" void kernel_launch(void* const* d_in, const int* in_sizes, int n_in,
                              void* d_out, int out_size)
{
    const float* x  = (const float*)d_in[0];
    const float* Wq = (const float*)d_in[1];
    const float* bq = (const float*)d_in[2];
    const float* Wk = (const float*)d_in[3];
    const float* bk = (const float*)d_in[4];
    const float* Wv = (const float*)d_in[5];
    const float* bv = (const float*)d_in[6];
    float* out = (float*)d_out;

    void *xr, *wqt, *wkt, *wvt, *q, *k, *vt, *s, *p;
    cudaGetSymbolAddress(&xr, g_xr);
    cudaGetSymbolAddress(&wqt, g_wqt); cudaGetSymbolAddress(&wkt, g_wkt); cudaGetSymbolAddress(&wvt, g_wvt);
    cudaGetSymbolAddress(&q, g_q); cudaGetSymbolAddress(&k, g_k);
    cudaGetSymbolAddress(&vt, g_vt);
    cudaGetSymbolAddress(&s, g_s); cudaGetSymbolAddress(&p, g_p);

    EncodeFn enc = nullptr;
    {
        void* fp = nullptr;
        cudaDriverEntryPointQueryResult qr;
        cudaGetDriverEntryPointByVersion("cuTensorMapEncodeTiled", &fp, 12000,
                                         cudaEnableDefault, &qr);
        enc = (EncodeFn)fp;
    }
    CUtensorMap tm_x, tm_wq, tm_wk, tm_wv, tm_q, tm_k, tm_p, tm_vt;
    make2d(enc, &tm_x,  xr,  8192, 1024);
    make2d(enc, &tm_wq, wqt, 1024, 1024);
    make2d(enc, &tm_wk, wkt, 1024, 1024);
    make2d(enc, &tm_wv, wvt, 1024, 1024);
    make2d(enc, &tm_q,  q,   8192, 1024);
    make2d(enc, &tm_k,  k,   8192, 1024);
    make2d(enc, &tm_p,  p,   8192, 2048);
    make2d(enc, &tm_vt, vt,  4096, 2048);

    cudaFuncSetAttribute(proj_qkv, cudaFuncAttributeMaxDynamicSharedMemorySize, DSMEM);
    cudaFuncSetAttribute(gemm_tma, cudaFuncAttributeMaxDynamicSharedMemorySize, DSMEM);

    const int MQ = BATCH * SEQ; // 8192

    // launch 0: round x -> tf32 values
    round_kernel<<<MQ * DMODEL / 4 / 256, 256>>>((const float4*)x, (float4*)xr, MQ * DMODEL / 4);

    // launch 1: transpose + round all weights
    dim3 gw(DMODEL / 32, DMODEL / 32, 3);
    wtrans3_kernel<<<gw, 256>>>(Wq, Wk, Wv, (float*)wqt, (float*)wkt, (float*)wvt);

    // launch 2: merged QKV projections (z = q/k/v)
    dim3 gp(DMODEL / 128, MQ / 128, 3);
    proj_qkv<<<gp, 256, DSMEM>>>(tm_x, tm_wq, tm_wk, tm_wv, bq, bk, bv,
                                 (float*)q, (float*)k, (float*)vt);

    // launch 3: scores = Q K^T / 32, batched over z
    dim3 gs(SEQ / 128, SEQ / 128, BATCH);
    gemm_tma<<<gs, 256, DSMEM>>>(tm_q, tm_k, (float*)s, SEQ,
                                 (long long)SEQ * SEQ, 0.03125f, DMODEL, SEQ, SEQ);

    // launch 4: softmax
    softmax_kernel<<<BATCH * SEQ, 256>>>((const float*)s, (float*)p);

    // launch 5 (profiled): out = P V
    dim3 go(DMODEL / 128, SEQ / 128, BATCH);
    gemm_tma<<<go, 256, DSMEM>>>(tm_p, tm_vt, out, DMODEL,
                                 (long long)SEQ * DMODEL, 1.0f, SEQ, SEQ, DMODEL);
}

// round 10
// speedup vs baseline: 3.4954x; 1.8047x over previous
#include <cuda_runtime.h>
#include <cuda.h>
#include <cuda_fp16.h>
#include <cstdint>
#include <math.h>

#define BATCH 4
#define SEQ   2048
#define DMODEL 1024

// ---------------- device scratch ----------------
__device__ __align__(128) __half g_xh[8388608];                // x fp16 [8192][1024]
__device__ __align__(128) __half g_wqt[1048576];
__device__ __align__(128) __half g_wkt[1048576];
__device__ __align__(128) __half g_wvt[1048576];
__device__ __align__(128) __half g_q[8388608];
__device__ __align__(128) __half g_k[8388608];
__device__ __align__(128) __half g_vt[8388608];                // V^T [4096][2048]
__device__ __align__(128) float  g_s[16777216];                // scores fp32
__device__ __align__(128) __half g_p[16777216];                // probs fp16

// ---------------- helpers ----------------
__device__ __forceinline__ uint32_t smem_u32(const void* p) {
    uint32_t a;
    asm("{ .reg .u64 t; cvta.to.shared.u64 t, %1; cvt.u32.u64 %0, t; }" : "=r"(a) : "l"(p));
    return a;
}
__device__ __forceinline__ void ldsm4(uint32_t* r, uint32_t a) {
    asm volatile("ldmatrix.sync.aligned.m8n8.x4.shared.b16 {%0,%1,%2,%3}, [%4];"
        : "=r"(r[0]), "=r"(r[1]), "=r"(r[2]), "=r"(r[3]) : "r"(a));
}
__device__ __forceinline__ void mma_f16(float* c, const uint32_t* a, const uint32_t* b) {
    asm volatile("mma.sync.aligned.m16n8k16.row.col.f32.f16.f16.f32 "
        "{%0,%1,%2,%3}, {%4,%5,%6,%7}, {%8,%9}, {%0,%1,%2,%3};"
        : "+f"(c[0]), "+f"(c[1]), "+f"(c[2]), "+f"(c[3])
        : "r"(a[0]), "r"(a[1]), "r"(a[2]), "r"(a[3]), "r"(b[0]), "r"(b[1]));
}
#define MBAR_INIT(a, c)  asm volatile("mbarrier.init.shared.b64 [%0], %1;" :: "r"(a), "r"(c) : "memory")
#define MBAR_EXPECT(a, b) asm volatile("mbarrier.arrive.expect_tx.shared.b64 _, [%0], %1;" :: "r"(a), "r"(b) : "memory")
#define FENCE_ASYNC()    asm volatile("fence.proxy.async.shared::cta;" ::: "memory")

__device__ __forceinline__ void mbar_wait(uint32_t mbar, uint32_t parity) {
    uint32_t done;
    asm volatile("{\n\t.reg .pred p;\n\t"
        "mbarrier.try_wait.parity.acquire.cta.shared::cta.b64 p, [%1], %2;\n\t"
        "selp.b32 %0, 1, 0, p;\n\t}"
        : "=r"(done) : "r"(mbar), "r"(parity) : "memory");
    while (!done) {
        asm volatile("{\n\t.reg .pred p;\n\t"
            "mbarrier.try_wait.parity.acquire.cta.shared::cta.b64 p, [%1], %2, 0x989680;\n\t"
            "selp.b32 %0, 1, 0, p;\n\t}"
            : "=r"(done) : "r"(mbar), "r"(parity) : "memory");
    }
}
__device__ __forceinline__ void tma2d(uint32_t dst, const CUtensorMap* tm, int x, int y, uint32_t mbar) {
    asm volatile("cp.async.bulk.tensor.2d.shared::cta.global.tile.mbarrier::complete_tx::bytes "
        "[%0], [%1, {%2, %3}], [%4];"
        :: "r"(dst), "l"(tm), "r"(x), "r"(y), "r"(mbar) : "memory");
}

// ---------------- prep kernels ----------------
__global__ __launch_bounds__(256) void cvt_kernel(const float4* __restrict__ X,
                                                  uint2* __restrict__ Y, int n4) {
    int i = blockIdx.x * 256 + threadIdx.x;
    if (i >= n4) return;
    float4 v = X[i];
    __half2 h0 = __floats2half2_rn(v.x, v.y);
    __half2 h1 = __floats2half2_rn(v.z, v.w);
    uint2 u;
    u.x = *reinterpret_cast<uint32_t*>(&h0);
    u.y = *reinterpret_cast<uint32_t*>(&h1);
    Y[i] = u;
}

__global__ __launch_bounds__(256) void wtrans3_kernel(
    const float* __restrict__ Wq, const float* __restrict__ Wk, const float* __restrict__ Wv,
    __half* __restrict__ Tq, __half* __restrict__ Tk, __half* __restrict__ Tv)
{
    const float* W = (blockIdx.z == 0) ? Wq : (blockIdx.z == 1) ? Wk : Wv;
    __half* T = (blockIdx.z == 0) ? Tq : (blockIdx.z == 1) ? Tk : Tv;

    __shared__ float t[32][33];
    int k0 = blockIdx.y * 32, n0 = blockIdx.x * 32;
    int tx = threadIdx.x & 31, ty = threadIdx.x >> 5;
    #pragma unroll
    for (int i = 0; i < 4; i++) {
        int k = ty + i * 8;
        t[k][tx] = W[(long long)(k0 + k) * DMODEL + n0 + tx];
    }
    __syncthreads();
    #pragma unroll
    for (int i = 0; i < 4; i++) {
        int n = ty + i * 8;
        T[(long long)(n0 + n) * DMODEL + k0 + tx] = __float2half_rn(t[tx][n]);
    }
}

// ---------------- shared GEMM plumbing ----------------
// fp16 tiles: 128 rows x 64 halfs (=128B, SW128). KC=64.
#define KC 64
#define TILE_B 16384                  // 128 rows x 128 B
#define STAGE_B (2 * TILE_B)          // A + B
#define NSTAGE 3
#define DSMEM (1024 + NSTAGE * STAGE_B + 64)

// mainloop: fills acc[2][8][4]; 4 k16 steps per chunk, interleaved ldsm/MMA
#define GEMM_MAINLOOP(tmAp, tmBp, mrow0, nrow0)                                           \
    if (tid == 0) {                                                                       \
        _Pragma("unroll")                                                                 \
        for (int s = 0; s < NSTAGE; s++) MBAR_INIT(ctrl + s * 8, 1);                      \
        FENCE_ASYNC();                                                                    \
    }                                                                                     \
    __syncthreads();                                                                      \
    if (tid == 0) {                                                                       \
        _Pragma("unroll")                                                                 \
        for (int s = 0; s < NSTAGE; s++) {                                                \
            if (s < CH) {                                                                 \
                MBAR_EXPECT(ctrl + s * 8, 2 * TILE_B);                                    \
                tma2d(tiles + s * STAGE_B,          tmAp, s * KC, (mrow0), ctrl + s * 8); \
                tma2d(tiles + s * STAGE_B + TILE_B, tmBp, s * KC, (nrow0), ctrl + s * 8); \
            }                                                                             \
        }                                                                                 \
    }                                                                                     \
    {                                                                                     \
        int stage = 0, phase = 0;                                                         \
        for (int c = 0; c < CH; c++) {                                                    \
            mbar_wait(ctrl + stage * 8, phase);                                           \
            const uint32_t stA = tiles + stage * STAGE_B;                                 \
            const uint32_t stB = stA + TILE_B;                                            \
            _Pragma("unroll")                                                             \
            for (int ks = 0; ks < 4; ks++) {                                              \
                const uint32_t kb = (qc + ks * 32) ^ xc;                                  \
                uint32_t a[2][4];                                                         \
                ldsm4(a[0], stA + aoff[0] + kb);                                          \
                ldsm4(a[1], stA + aoff[1] + kb);                                          \
                uint32_t bb[4][2];                                                        \
                {                                                                         \
                    uint32_t r[4];                                                        \
                    ldsm4(r, stB + boff[0] + kb);                                         \
                    bb[0][0] = r[0]; bb[0][1] = r[2];                                     \
                    bb[1][0] = r[1]; bb[1][1] = r[3];                                     \
                    ldsm4(r, stB + boff[1] + kb);                                         \
                    bb[2][0] = r[0]; bb[2][1] = r[2];                                     \
                    bb[3][0] = r[1]; bb[3][1] = r[3];                                     \
                }                                                                         \
                _Pragma("unroll")                                                         \
                for (int nt = 0; nt < 4; nt++) {                                          \
                    mma_f16(acc[0][nt], a[0], bb[nt]);                                    \
                    mma_f16(acc[1][nt], a[1], bb[nt]);                                    \
                }                                                                         \
                {                                                                         \
                    uint32_t r[4];                                                        \
                    ldsm4(r, stB + boff[2] + kb);                                         \
                    bb[0][0] = r[0]; bb[0][1] = r[2];                                     \
                    bb[1][0] = r[1]; bb[1][1] = r[3];                                     \
                    ldsm4(r, stB + boff[3] + kb);                                         \
                    bb[2][0] = r[0]; bb[2][1] = r[2];                                     \
                    bb[3][0] = r[1]; bb[3][1] = r[3];                                     \
                }                                                                         \
                _Pragma("unroll")                                                         \
                for (int nt = 0; nt < 4; nt++) {                                          \
                    mma_f16(acc[0][4 + nt], a[0], bb[nt]);                                \
                    mma_f16(acc[1][4 + nt], a[1], bb[nt]);                                \
                }                                                                         \
            }                                                                             \
            __syncthreads();                                                              \
            if (tid == 0 && c + NSTAGE < CH) {                                            \
                const int cn = c + NSTAGE;                                                \
                MBAR_EXPECT(ctrl + stage * 8, 2 * TILE_B);                                \
                tma2d(tiles + stage * STAGE_B,          tmAp, cn * KC, (mrow0), ctrl + stage * 8); \
                tma2d(tiles + stage * STAGE_B + TILE_B, tmBp, cn * KC, (nrow0), ctrl + stage * 8); \
            }                                                                             \
            if (++stage == NSTAGE) { stage = 0; phase ^= 1; }                             \
        }                                                                                 \
    }                                                                                     \
    __syncthreads();

// fragment addressing for fp16 b16 ldsm (16x16 tiles), SW128-swizzled
#define FRAG_ADDR_SETUP()                                                \
    const uint32_t xc = (lane & 7) << 4;                                 \
    const uint32_t qc = (lane >> 4) << 4;                                \
    uint32_t aoff[2], boff[4];                                           \
    _Pragma("unroll")                                                    \
    for (int mt = 0; mt < 2; mt++)                                       \
        aoff[mt] = (wm * 32 + mt * 16 + (lane & 15)) * 128;              \
    _Pragma("unroll")                                                    \
    for (int nt2 = 0; nt2 < 4; nt2++)                                    \
        boff[nt2] = (wn * 64 + nt2 * 16 + (lane & 15)) * 128;

// ---------------- merged QKV projection (z selects q/k/v) ----------------
__global__ __launch_bounds__(256, 2)
void proj_qkv(const __grid_constant__ CUtensorMap tmX,
              const __grid_constant__ CUtensorMap tmWq,
              const __grid_constant__ CUtensorMap tmWk,
              const __grid_constant__ CUtensorMap tmWv,
              const float* __restrict__ bq, const float* __restrict__ bk, const float* __restrict__ bv,
              __half* __restrict__ Q, __half* __restrict__ Kmat, __half* __restrict__ VT)
{
    extern __shared__ char smem[];
    const uint32_t sbase = smem_u32(smem);
    const uint32_t tiles = (sbase + 1023) & ~1023u;
    const uint32_t ctrl  = tiles + NSTAGE * STAGE_B;

    const int tid = threadIdx.x, lane = tid & 31, wid = tid >> 5;
    const int wm = wid & 3, wn = wid >> 2;
    const int z = blockIdx.z;
    const int m0 = blockIdx.y * 128, n0 = blockIdx.x * 128;

    const CUtensorMap* tb = (z == 0) ? &tmWq : (z == 1) ? &tmWk : &tmWv;
    const float* bias = (z == 0) ? bq : (z == 1) ? bk : bv;

    FRAG_ADDR_SETUP()

    float acc[2][8][4] = {};
    const int CH = DMODEL / KC;

    GEMM_MAINLOOP(&tmX, tb, m0, n0)

    if (z == 2) {
        // V: transposed output (V^T layout, batches stacked)
        float* stg = (float*)smem;
        #pragma unroll
        for (int mt = 0; mt < 2; mt++)
            #pragma unroll
            for (int h = 0; h < 2; h++) {
                int m = wm * 32 + mt * 16 + (lane >> 2) + h * 8;
                #pragma unroll
                for (int nt = 0; nt < 8; nt++) {
                    int n = wn * 64 + nt * 8 + ((lane & 3) << 1);
                    stg[m * 133 + n]     = acc[mt][nt][h * 2 + 0] + __ldg(bias + n0 + n);
                    stg[m * 133 + n + 1] = acc[mt][nt][h * 2 + 1] + __ldg(bias + n0 + n + 1);
                }
            }
        __syncthreads();
        #pragma unroll 4
        for (int i = 0; i < 64; i++) {
            int linear = i * 256 + tid;
            int n = linear >> 7, m = linear & 127;
            float v = stg[m * 133 + n];
            int gm = m0 + m;
            long long idx = ((long long)(gm >> 11) * DMODEL + (n0 + n)) * SEQ + (gm & (SEQ - 1));
            VT[idx] = __float2half_rn(v);
        }
    } else {
        __half* C = (z == 0) ? Q : Kmat;
        #pragma unroll
        for (int mt = 0; mt < 2; mt++)
            #pragma unroll
            for (int h = 0; h < 2; h++) {
                int m = m0 + wm * 32 + mt * 16 + (lane >> 2) + h * 8;
                #pragma unroll
                for (int nt = 0; nt < 8; nt++) {
                    int n = n0 + wn * 64 + nt * 8 + ((lane & 3) << 1);
                    float v0 = acc[mt][nt][h * 2 + 0] + __ldg(bias + n);
                    float v1 = acc[mt][nt][h * 2 + 1] + __ldg(bias + n + 1);
                    __half2 hv = __floats2half2_rn(v0, v1);
                    *(__half2*)(C + (long long)m * DMODEL + n) = hv;
                }
            }
    }
}

// ---------------- generic TMA GEMM (scores / PV): fp32 C = scale*(A·B^T) ----------------
__global__ __launch_bounds__(256, 2)
void gemm_tma(const __grid_constant__ CUtensorMap tmA,
              const __grid_constant__ CUtensorMap tmB,
              float* __restrict__ C, int ldC, long long sC,
              float scale, int K, int mBatchRows, int nBatchRows)
{
    extern __shared__ char smem[];
    const uint32_t sbase = smem_u32(smem);
    const uint32_t tiles = (sbase + 1023) & ~1023u;
    const uint32_t ctrl  = tiles + NSTAGE * STAGE_B;

    const int tid = threadIdx.x, lane = tid & 31, wid = tid >> 5;
    const int wm = wid & 3, wn = wid >> 2;
    const int z = blockIdx.z;
    C += (long long)z * sC;
    const int m0 = blockIdx.y * 128, n0 = blockIdx.x * 128;
    const int mrow0 = m0 + z * mBatchRows;
    const int nrow0 = n0 + z * nBatchRows;

    FRAG_ADDR_SETUP()

    float acc[2][8][4] = {};
    const int CH = K / KC;

    GEMM_MAINLOOP(&tmA, &tmB, mrow0, nrow0)

    #pragma unroll
    for (int mt = 0; mt < 2; mt++)
        #pragma unroll
        for (int h = 0; h < 2; h++) {
            int m = m0 + wm * 32 + mt * 16 + (lane >> 2) + h * 8;
            #pragma unroll
            for (int nt = 0; nt < 8; nt++) {
                int n = n0 + wn * 64 + nt * 8 + ((lane & 3) << 1);
                float2 f;
                f.x = acc[mt][nt][h * 2 + 0] * scale;
                f.y = acc[mt][nt][h * 2 + 1] * scale;
                *(float2*)(C + (long long)m * ldC + n) = f;
            }
        }
}

// ---------------- softmax: fp32 scores -> fp16 probs ----------------
__global__ __launch_bounds__(256) void softmax_kernel(const float* __restrict__ S,
                                                      __half* __restrict__ P) {
    const long long row = blockIdx.x;
    const float* p = S + row * SEQ;
    const int tid = threadIdx.x, lane = tid & 31, w = tid >> 5;
    __shared__ float red[8];

    float vals[8];
    const float4 a = *(const float4*)(p + tid * 8);
    const float4 b = *(const float4*)(p + tid * 8 + 4);
    vals[0]=a.x; vals[1]=a.y; vals[2]=a.z; vals[3]=a.w;
    vals[4]=b.x; vals[5]=b.y; vals[6]=b.z; vals[7]=b.w;

    float m = -INFINITY;
    #pragma unroll
    for (int i = 0; i < 8; i++) m = fmaxf(m, vals[i]);
    #pragma unroll
    for (int o = 16; o; o >>= 1) m = fmaxf(m, __shfl_xor_sync(0xffffffffu, m, o));
    if (lane == 0) red[w] = m;
    __syncthreads();
    if (w == 0) {
        float x = red[lane & 7];
        #pragma unroll
        for (int o = 4; o; o >>= 1) x = fmaxf(x, __shfl_xor_sync(0xffffffffu, x, o));
        if (lane == 0) red[0] = x;
    }
    __syncthreads();
    m = red[0];
    __syncthreads();

    float s = 0.0f;
    #pragma unroll
    for (int i = 0; i < 8; i++) { vals[i] = __expf(vals[i] - m); s += vals[i]; }
    #pragma unroll
    for (int o = 16; o; o >>= 1) s += __shfl_xor_sync(0xffffffffu, s, o);
    if (lane == 0) red[w] = s;
    __syncthreads();
    if (w == 0) {
        float x = red[lane & 7];
        #pragma unroll
        for (int o = 4; o; o >>= 1) x += __shfl_xor_sync(0xffffffffu, x, o);
        if (lane == 0) red[0] = x;
    }
    __syncthreads();
    const float inv = 1.0f / red[0];

    __half2 h0 = __floats2half2_rn(vals[0] * inv, vals[1] * inv);
    __half2 h1 = __floats2half2_rn(vals[2] * inv, vals[3] * inv);
    __half2 h2 = __floats2half2_rn(vals[4] * inv, vals[5] * inv);
    __half2 h3 = __floats2half2_rn(vals[6] * inv, vals[7] * inv);
    uint4 u;
    u.x = *reinterpret_cast<uint32_t*>(&h0);
    u.y = *reinterpret_cast<uint32_t*>(&h1);
    u.z = *reinterpret_cast<uint32_t*>(&h2);
    u.w = *reinterpret_cast<uint32_t*>(&h3);
    *(uint4*)(P + row * SEQ + tid * 8) = u;
}

// ---------------- host: tensormap encode via driver entry point ----------------
typedef CUresult (*EncodeFn)(CUtensorMap*, CUtensorMapDataType, cuuint32_t, void*,
                             const cuuint64_t*, const cuuint64_t*, const cuuint32_t*,
                             const cuuint32_t*, CUtensorMapInterleave, CUtensorMapSwizzle,
                             CUtensorMapL2promotion, CUtensorMapFloatOOBfill);

static void make2d_h(EncodeFn enc, CUtensorMap* m, void* p, unsigned long long rows, unsigned long long cols) {
    cuuint64_t dims[2]    = {cols, rows};
    cuuint64_t strides[1] = {cols * 2};
    cuuint32_t box[2]     = {64, 128};       // 64 fp16 = 128B (SW128 limit)
    cuuint32_t es[2]      = {1, 1};
    enc(m, CU_TENSOR_MAP_DATA_TYPE_FLOAT16, 2, p, dims, strides, box, es,
        CU_TENSOR_MAP_INTERLEAVE_NONE, CU_TENSOR_MAP_SWIZZLE_128B,
        CU_TENSOR_MAP_L2_PROMOTION_L2_128B, CU_TENSOR_MAP_FLOAT_OOB_FILL_NONE);
}

// ---------------- launch ----------------
extern "C" void kernel_launch(void* const* d_in, const int* in_sizes, int n_in,
                              void* d_out, int out_size)
{
    const float* x  = (const float*)d_in[0];
    const float* Wq = (const float*)d_in[1];
    const float* bq = (const float*)d_in[2];
    const float* Wk = (const float*)d_in[3];
    const float* bk = (const float*)d_in[4];
    const float* Wv = (const float*)d_in[5];
    const float* bv = (const float*)d_in[6];
    float* out = (float*)d_out;

    void *xh, *wqt, *wkt, *wvt, *q, *k, *vt, *s, *p;
    cudaGetSymbolAddress(&xh, g_xh);
    cudaGetSymbolAddress(&wqt, g_wqt); cudaGetSymbolAddress(&wkt, g_wkt); cudaGetSymbolAddress(&wvt, g_wvt);
    cudaGetSymbolAddress(&q, g_q); cudaGetSymbolAddress(&k, g_k);
    cudaGetSymbolAddress(&vt, g_vt);
    cudaGetSymbolAddress(&s, g_s); cudaGetSymbolAddress(&p, g_p);

    EncodeFn enc = nullptr;
    {
        void* fp = nullptr;
        cudaDriverEntryPointQueryResult qr;
        cudaGetDriverEntryPointByVersion("cuTensorMapEncodeTiled", &fp, 12000,
                                         cudaEnableDefault, &qr);
        enc = (EncodeFn)fp;
    }
    CUtensorMap tm_x, tm_wq, tm_wk, tm_wv, tm_q, tm_k, tm_p, tm_vt;
    make2d_h(enc, &tm_x,  xh,  8192, 1024);
    make2d_h(enc, &tm_wq, wqt, 1024, 1024);
    make2d_h(enc, &tm_wk, wkt, 1024, 1024);
    make2d_h(enc, &tm_wv, wvt, 1024, 1024);
    make2d_h(enc, &tm_q,  q,   8192, 1024);
    make2d_h(enc, &tm_k,  k,   8192, 1024);
    make2d_h(enc, &tm_p,  p,   8192, 2048);
    make2d_h(enc, &tm_vt, vt,  4096, 2048);

    cudaFuncSetAttribute(proj_qkv, cudaFuncAttributeMaxDynamicSharedMemorySize, DSMEM);
    cudaFuncSetAttribute(gemm_tma, cudaFuncAttributeMaxDynamicSharedMemorySize, DSMEM);

    const int MQ = BATCH * SEQ; // 8192

    // launch 0: convert x -> fp16
    cvt_kernel<<<MQ * DMODEL / 4 / 256, 256>>>((const float4*)x, (uint2*)xh, MQ * DMODEL / 4);

    // launch 1: transpose + convert all weights
    dim3 gw(DMODEL / 32, DMODEL / 32, 3);
    wtrans3_kernel<<<gw, 256>>>(Wq, Wk, Wv, (__half*)wqt, (__half*)wkt, (__half*)wvt);

    // launch 2: merged QKV projections (z = q/k/v)
    dim3 gp(DMODEL / 128, MQ / 128, 3);
    proj_qkv<<<gp, 256, DSMEM>>>(tm_x, tm_wq, tm_wk, tm_wv, bq, bk, bv,
                                 (__half*)q, (__half*)k, (__half*)vt);

    // launch 3: scores = Q K^T / 32, batched over z
    dim3 gs(SEQ / 128, SEQ / 128, BATCH);
    gemm_tma<<<gs, 256, DSMEM>>>(tm_q, tm_k, (float*)s, SEQ,
                                 (long long)SEQ * SEQ, 0.03125f, DMODEL, SEQ, SEQ);

    // launch 4: softmax
    softmax_kernel<<<BATCH * SEQ, 256>>>((const float*)s, (__half*)p);

    // launch 5 (profiled): out = P V
    dim3 go(DMODEL / 128, SEQ / 128, BATCH);
    gemm_tma<<<go, 256, DSMEM>>>(tm_p, tm_vt, out, DMODEL,
                                 (long long)SEQ * DMODEL, 1.0f, SEQ, SEQ, DMODEL);
}

// round 11
// speedup vs baseline: 3.5816x; 1.0247x over previous
#include <cuda_runtime.h>
#include <cuda.h>
#include <cuda_fp16.h>
#include <cstdint>
#include <math.h>

#define BATCH 4
#define SEQ   2048
#define DMODEL 1024

// ---------------- device scratch ----------------
__device__ __align__(128) __half g_xh[8388608];                // x fp16 [8192][1024]
__device__ __align__(128) __half g_wqt[1048576];
__device__ __align__(128) __half g_wkt[1048576];
__device__ __align__(128) __half g_wvt[1048576];
__device__ __align__(128) __half g_q[8388608];
__device__ __align__(128) __half g_k[8388608];
__device__ __align__(128) __half g_vt[8388608];                // V^T [4096][2048]
__device__ __align__(128) float  g_s[16777216];                // scores fp32
__device__ __align__(128) __half g_p[16777216];                // probs fp16

// ---------------- helpers ----------------
__device__ __forceinline__ uint32_t smem_u32(const void* p) {
    uint32_t a;
    asm("{ .reg .u64 t; cvta.to.shared.u64 t, %1; cvt.u32.u64 %0, t; }" : "=r"(a) : "l"(p));
    return a;
}
__device__ __forceinline__ void ldsm4(uint32_t* r, uint32_t a) {
    asm volatile("ldmatrix.sync.aligned.m8n8.x4.shared.b16 {%0,%1,%2,%3}, [%4];"
        : "=r"(r[0]), "=r"(r[1]), "=r"(r[2]), "=r"(r[3]) : "r"(a));
}
__device__ __forceinline__ void mma_f16(float* c, const uint32_t* a, const uint32_t* b) {
    asm volatile("mma.sync.aligned.m16n8k16.row.col.f32.f16.f16.f32 "
        "{%0,%1,%2,%3}, {%4,%5,%6,%7}, {%8,%9}, {%0,%1,%2,%3};"
        : "+f"(c[0]), "+f"(c[1]), "+f"(c[2]), "+f"(c[3])
        : "r"(a[0]), "r"(a[1]), "r"(a[2]), "r"(a[3]), "r"(b[0]), "r"(b[1]));
}
#define MBAR_INIT(a, c)   asm volatile("mbarrier.init.shared.b64 [%0], %1;" :: "r"(a), "r"(c) : "memory")
#define MBAR_EXPECT(a, b) asm volatile("mbarrier.arrive.expect_tx.shared.b64 _, [%0], %1;" :: "r"(a), "r"(b) : "memory")
#define MBAR_ARRIVE(a)    asm volatile("mbarrier.arrive.shared.b64 _, [%0];" :: "r"(a) : "memory")
#define FENCE_ASYNC()     asm volatile("fence.proxy.async.shared::cta;" ::: "memory")

__device__ __forceinline__ void mbar_wait(uint32_t mbar, uint32_t parity) {
    uint32_t done;
    asm volatile("{\n\t.reg .pred p;\n\t"
        "mbarrier.try_wait.parity.acquire.cta.shared::cta.b64 p, [%1], %2;\n\t"
        "selp.b32 %0, 1, 0, p;\n\t}"
        : "=r"(done) : "r"(mbar), "r"(parity) : "memory");
    while (!done) {
        asm volatile("{\n\t.reg .pred p;\n\t"
            "mbarrier.try_wait.parity.acquire.cta.shared::cta.b64 p, [%1], %2, 0x989680;\n\t"
            "selp.b32 %0, 1, 0, p;\n\t}"
            : "=r"(done) : "r"(mbar), "r"(parity) : "memory");
    }
}
__device__ __forceinline__ void tma2d(uint32_t dst, const CUtensorMap* tm, int x, int y, uint32_t mbar) {
    asm volatile("cp.async.bulk.tensor.2d.shared::cta.global.tile.mbarrier::complete_tx::bytes "
        "[%0], [%1, {%2, %3}], [%4];"
        :: "r"(dst), "l"(tm), "r"(x), "r"(y), "r"(mbar) : "memory");
}

// ---------------- prep kernels ----------------
__global__ __launch_bounds__(256) void cvt_kernel(const float4* __restrict__ X,
                                                  uint2* __restrict__ Y, int n4) {
    int i = blockIdx.x * 256 + threadIdx.x;
    if (i >= n4) return;
    float4 v = X[i];
    __half2 h0 = __floats2half2_rn(v.x, v.y);
    __half2 h1 = __floats2half2_rn(v.z, v.w);
    uint2 u;
    u.x = *reinterpret_cast<uint32_t*>(&h0);
    u.y = *reinterpret_cast<uint32_t*>(&h1);
    Y[i] = u;
}

__global__ __launch_bounds__(256) void wtrans3_kernel(
    const float* __restrict__ Wq, const float* __restrict__ Wk, const float* __restrict__ Wv,
    __half* __restrict__ Tq, __half* __restrict__ Tk, __half* __restrict__ Tv)
{
    const float* W = (blockIdx.z == 0) ? Wq : (blockIdx.z == 1) ? Wk : Wv;
    __half* T = (blockIdx.z == 0) ? Tq : (blockIdx.z == 1) ? Tk : Tv;

    __shared__ float t[32][33];
    int k0 = blockIdx.y * 32, n0 = blockIdx.x * 32;
    int tx = threadIdx.x & 31, ty = threadIdx.x >> 5;
    #pragma unroll
    for (int i = 0; i < 4; i++) {
        int k = ty + i * 8;
        t[k][tx] = W[(long long)(k0 + k) * DMODEL + n0 + tx];
    }
    __syncthreads();
    #pragma unroll
    for (int i = 0; i < 4; i++) {
        int n = ty + i * 8;
        T[(long long)(n0 + n) * DMODEL + k0 + tx] = __float2half_rn(t[tx][n]);
    }
}

// ---------------- shared GEMM plumbing ----------------
// fp16 tiles: 128 rows x 64 halfs (=128B, SW128). KC=64.
#define KC 64
#define TILE_B 16384                  // 128 rows x 128 B
#define STAGE_B (2 * TILE_B)          // A + B
#define NSTAGE 3
#define DSMEM (1024 + NSTAGE * STAGE_B + 128)

// ctrl layout: per stage s: full mbar at ctrl+s*16, empty mbar at ctrl+s*16+8
// Producer/consumer pipeline, no block-wide barrier in the mainloop.
#define GEMM_MAINLOOP(tmAp, tmBp, mrow0, nrow0)                                           \
    if (tid == 0) {                                                                       \
        _Pragma("unroll")                                                                 \
        for (int s = 0; s < NSTAGE; s++) {                                                \
            MBAR_INIT(ctrl + s * 16, 1);                                                  \
            MBAR_INIT(ctrl + s * 16 + 8, 8);                                              \
        }                                                                                 \
        FENCE_ASYNC();                                                                    \
    }                                                                                     \
    __syncthreads();                                                                      \
    if (tid == 0) {                                                                       \
        _Pragma("unroll")                                                                 \
        for (int s = 0; s < NSTAGE; s++) {                                                \
            if (s < CH) {                                                                 \
                MBAR_EXPECT(ctrl + s * 16, 2 * TILE_B);                                   \
                tma2d(tiles + s * STAGE_B,          tmAp, s * KC, (mrow0), ctrl + s * 16);\
                tma2d(tiles + s * STAGE_B + TILE_B, tmBp, s * KC, (nrow0), ctrl + s * 16);\
            }                                                                             \
        }                                                                                 \
    }                                                                                     \
    {                                                                                     \
        int stage = 0, phase = 0;                                                         \
        for (int c = 0; c < CH; c++) {                                                    \
            mbar_wait(ctrl + stage * 16, phase);                                          \
            const uint32_t stA = tiles + stage * STAGE_B;                                 \
            const uint32_t stB = stA + TILE_B;                                            \
            _Pragma("unroll")                                                             \
            for (int ks = 0; ks < 4; ks++) {                                              \
                const uint32_t kb = (qc + ks * 32) ^ xc;                                  \
                uint32_t a[2][4];                                                         \
                ldsm4(a[0], stA + aoff[0] + kb);                                          \
                ldsm4(a[1], stA + aoff[1] + kb);                                          \
                uint32_t bb[4][2];                                                        \
                {                                                                         \
                    uint32_t r[4];                                                        \
                    ldsm4(r, stB + boff[0] + kb);                                         \
                    bb[0][0] = r[0]; bb[0][1] = r[2];                                     \
                    bb[1][0] = r[1]; bb[1][1] = r[3];                                     \
                    ldsm4(r, stB + boff[1] + kb);                                         \
                    bb[2][0] = r[0]; bb[2][1] = r[2];                                     \
                    bb[3][0] = r[1]; bb[3][1] = r[3];                                     \
                }                                                                         \
                _Pragma("unroll")                                                         \
                for (int nt = 0; nt < 4; nt++) {                                          \
                    mma_f16(acc[0][nt], a[0], bb[nt]);                                    \
                    mma_f16(acc[1][nt], a[1], bb[nt]);                                    \
                }                                                                         \
                {                                                                         \
                    uint32_t r[4];                                                        \
                    ldsm4(r, stB + boff[2] + kb);                                         \
                    bb[0][0] = r[0]; bb[0][1] = r[2];                                     \
                    bb[1][0] = r[1]; bb[1][1] = r[3];                                     \
                    ldsm4(r, stB + boff[3] + kb);                                         \
                    bb[2][0] = r[0]; bb[2][1] = r[2];                                     \
                    bb[3][0] = r[1]; bb[3][1] = r[3];                                     \
                }                                                                         \
                _Pragma("unroll")                                                         \
                for (int nt = 0; nt < 4; nt++) {                                          \
                    mma_f16(acc[0][4 + nt], a[0], bb[nt]);                                \
                    mma_f16(acc[1][4 + nt], a[1], bb[nt]);                                \
                }                                                                         \
            }                                                                             \
            if (lane == 0) MBAR_ARRIVE(ctrl + stage * 16 + 8);                            \
            if (tid == 0 && c + NSTAGE < CH) {                                            \
                mbar_wait(ctrl + stage * 16 + 8, phase);                                  \
                const int cn = c + NSTAGE;                                                \
                MBAR_EXPECT(ctrl + stage * 16, 2 * TILE_B);                               \
                tma2d(tiles + stage * STAGE_B,          tmAp, cn * KC, (mrow0), ctrl + stage * 16); \
                tma2d(tiles + stage * STAGE_B + TILE_B, tmBp, cn * KC, (nrow0), ctrl + stage * 16); \
            }                                                                             \
            if (++stage == NSTAGE) { stage = 0; phase ^= 1; }                             \
        }                                                                                 \
    }                                                                                     \
    __syncthreads();

// fragment addressing for fp16 b16 ldsm (16x16 tiles), SW128-swizzled
#define FRAG_ADDR_SETUP()                                                \
    const uint32_t xc = (lane & 7) << 4;                                 \
    const uint32_t qc = (lane >> 4) << 4;                                \
    uint32_t aoff[2], boff[4];                                           \
    _Pragma("unroll")                                                    \
    for (int mt = 0; mt < 2; mt++)                                       \
        aoff[mt] = (wm * 32 + mt * 16 + (lane & 15)) * 128;              \
    _Pragma("unroll")                                                    \
    for (int nt2 = 0; nt2 < 4; nt2++)                                    \
        boff[nt2] = (wn * 64 + nt2 * 16 + (lane & 15)) * 128;

// ---------------- merged QKV projection (z selects q/k/v) ----------------
__global__ __launch_bounds__(256, 2)
void proj_qkv(const __grid_constant__ CUtensorMap tmX,
              const __grid_constant__ CUtensorMap tmWq,
              const __grid_constant__ CUtensorMap tmWk,
              const __grid_constant__ CUtensorMap tmWv,
              const float* __restrict__ bq, const float* __restrict__ bk, const float* __restrict__ bv,
              __half* __restrict__ Q, __half* __restrict__ Kmat, __half* __restrict__ VT)
{
    extern __shared__ char smem[];
    const uint32_t sbase = smem_u32(smem);
    const uint32_t tiles = (sbase + 1023) & ~1023u;
    const uint32_t ctrl  = tiles + NSTAGE * STAGE_B;

    const int tid = threadIdx.x, lane = tid & 31, wid = tid >> 5;
    const int wm = wid & 3, wn = wid >> 2;
    const int z = blockIdx.z;
    const int m0 = blockIdx.y * 128, n0 = blockIdx.x * 128;

    const CUtensorMap* tb = (z == 0) ? &tmWq : (z == 1) ? &tmWk : &tmWv;
    const float* bias = (z == 0) ? bq : (z == 1) ? bk : bv;

    FRAG_ADDR_SETUP()

    float acc[2][8][4] = {};
    const int CH = DMODEL / KC;

    GEMM_MAINLOOP(&tmX, tb, m0, n0)

    if (z == 2) {
        // V: transposed output (V^T layout, batches stacked)
        float* stg = (float*)smem;
        #pragma unroll
        for (int mt = 0; mt < 2; mt++)
            #pragma unroll
            for (int h = 0; h < 2; h++) {
                int m = wm * 32 + mt * 16 + (lane >> 2) + h * 8;
                #pragma unroll
                for (int nt = 0; nt < 8; nt++) {
                    int n = wn * 64 + nt * 8 + ((lane & 3) << 1);
                    stg[m * 133 + n]     = acc[mt][nt][h * 2 + 0] + __ldg(bias + n0 + n);
                    stg[m * 133 + n + 1] = acc[mt][nt][h * 2 + 1] + __ldg(bias + n0 + n + 1);
                }
            }
        __syncthreads();
        #pragma unroll 4
        for (int i = 0; i < 64; i++) {
            int linear = i * 256 + tid;
            int n = linear >> 7, m = linear & 127;
            float v = stg[m * 133 + n];
            int gm = m0 + m;
            long long idx = ((long long)(gm >> 11) * DMODEL + (n0 + n)) * SEQ + (gm & (SEQ - 1));
            VT[idx] = __float2half_rn(v);
        }
    } else {
        __half* C = (z == 0) ? Q : Kmat;
        #pragma unroll
        for (int mt = 0; mt < 2; mt++)
            #pragma unroll
            for (int h = 0; h < 2; h++) {
                int m = m0 + wm * 32 + mt * 16 + (lane >> 2) + h * 8;
                #pragma unroll
                for (int nt = 0; nt < 8; nt++) {
                    int n = n0 + wn * 64 + nt * 8 + ((lane & 3) << 1);
                    float v0 = acc[mt][nt][h * 2 + 0] + __ldg(bias + n);
                    float v1 = acc[mt][nt][h * 2 + 1] + __ldg(bias + n + 1);
                    __half2 hv = __floats2half2_rn(v0, v1);
                    *(__half2*)(C + (long long)m * DMODEL + n) = hv;
                }
            }
    }
}

// ---------------- generic TMA GEMM (scores / PV): fp32 C = scale*(A·B^T) ----------------
__global__ __launch_bounds__(256, 2)
void gemm_tma(const __grid_constant__ CUtensorMap tmA,
              const __grid_constant__ CUtensorMap tmB,
              float* __restrict__ C, int ldC, long long sC,
              float scale, int K, int mBatchRows, int nBatchRows)
{
    extern __shared__ char smem[];
    const uint32_t sbase = smem_u32(smem);
    const uint32_t tiles = (sbase + 1023) & ~1023u;
    const uint32_t ctrl  = tiles + NSTAGE * STAGE_B;

    const int tid = threadIdx.x, lane = tid & 31, wid = tid >> 5;
    const int wm = wid & 3, wn = wid >> 2;
    const int z = blockIdx.z;
    C += (long long)z * sC;
    const int m0 = blockIdx.y * 128, n0 = blockIdx.x * 128;
    const int mrow0 = m0 + z * mBatchRows;
    const int nrow0 = n0 + z * nBatchRows;

    FRAG_ADDR_SETUP()

    float acc[2][8][4] = {};
    const int CH = K / KC;

    GEMM_MAINLOOP(&tmA, &tmB, mrow0, nrow0)

    #pragma unroll
    for (int mt = 0; mt < 2; mt++)
        #pragma unroll
        for (int h = 0; h < 2; h++) {
            int m = m0 + wm * 32 + mt * 16 + (lane >> 2) + h * 8;
            #pragma unroll
            for (int nt = 0; nt < 8; nt++) {
                int n = n0 + wn * 64 + nt * 8 + ((lane & 3) << 1);
                float2 f;
                f.x = acc[mt][nt][h * 2 + 0] * scale;
                f.y = acc[mt][nt][h * 2 + 1] * scale;
                *(float2*)(C + (long long)m * ldC + n) = f;
            }
        }
}

// ---------------- softmax: fp32 scores -> fp16 probs ----------------
__global__ __launch_bounds__(256) void softmax_kernel(const float* __restrict__ S,
                                                      __half* __restrict__ P) {
    const long long row = blockIdx.x;
    const float* p = S + row * SEQ;
    const int tid = threadIdx.x, lane = tid & 31, w = tid >> 5;
    __shared__ float red[8];

    float vals[8];
    const float4 a = *(const float4*)(p + tid * 8);
    const float4 b = *(const float4*)(p + tid * 8 + 4);
    vals[0]=a.x; vals[1]=a.y; vals[2]=a.z; vals[3]=a.w;
    vals[4]=b.x; vals[5]=b.y; vals[6]=b.z; vals[7]=b.w;

    float m = -INFINITY;
    #pragma unroll
    for (int i = 0; i < 8; i++) m = fmaxf(m, vals[i]);
    #pragma unroll
    for (int o = 16; o; o >>= 1) m = fmaxf(m, __shfl_xor_sync(0xffffffffu, m, o));
    if (lane == 0) red[w] = m;
    __syncthreads();
    if (w == 0) {
        float x = red[lane & 7];
        #pragma unroll
        for (int o = 4; o; o >>= 1) x = fmaxf(x, __shfl_xor_sync(0xffffffffu, x, o));
        if (lane == 0) red[0] = x;
    }
    __syncthreads();
    m = red[0];
    __syncthreads();

    float s = 0.0f;
    #pragma unroll
    for (int i = 0; i < 8; i++) { vals[i] = __expf(vals[i] - m); s += vals[i]; }
    #pragma unroll
    for (int o = 16; o; o >>= 1) s += __shfl_xor_sync(0xffffffffu, s, o);
    if (lane == 0) red[w] = s;
    __syncthreads();
    if (w == 0) {
        float x = red[lane & 7];
        #pragma unroll
        for (int o = 4; o; o >>= 1) x += __shfl_xor_sync(0xffffffffu, x, o);
        if (lane == 0) red[0] = x;
    }
    __syncthreads();
    const float inv = 1.0f / red[0];

    __half2 h0 = __floats2half2_rn(vals[0] * inv, vals[1] * inv);
    __half2 h1 = __floats2half2_rn(vals[2] * inv, vals[3] * inv);
    __half2 h2 = __floats2half2_rn(vals[4] * inv, vals[5] * inv);
    __half2 h3 = __floats2half2_rn(vals[6] * inv, vals[7] * inv);
    uint4 u;
    u.x = *reinterpret_cast<uint32_t*>(&h0);
    u.y = *reinterpret_cast<uint32_t*>(&h1);
    u.z = *reinterpret_cast<uint32_t*>(&h2);
    u.w = *reinterpret_cast<uint32_t*>(&h3);
    *(uint4*)(P + row * SEQ + tid * 8) = u;
}

// ---------------- host: tensormap encode via driver entry point ----------------
typedef CUresult (*EncodeFn)(CUtensorMap*, CUtensorMapDataType, cuuint32_t, void*,
                             const cuuint64_t*, const cuuint64_t*, const cuuint32_t*,
                             const cuuint32_t*, CUtensorMapInterleave, CUtensorMapSwizzle,
                             CUtensorMapL2promotion, CUtensorMapFloatOOBfill);

static void make2d_h(EncodeFn enc, CUtensorMap* m, void* p, unsigned long long rows, unsigned long long cols) {
    cuuint64_t dims[2]    = {cols, rows};
    cuuint64_t strides[1] = {cols * 2};
    cuuint32_t box[2]     = {64, 128};       // 64 fp16 = 128B (SW128 limit)
    cuuint32_t es[2]      = {1, 1};
    enc(m, CU_TENSOR_MAP_DATA_TYPE_FLOAT16, 2, p, dims, strides, box, es,
        CU_TENSOR_MAP_INTERLEAVE_NONE, CU_TENSOR_MAP_SWIZZLE_128B,
        CU_TENSOR_MAP_L2_PROMOTION_L2_128B, CU_TENSOR_MAP_FLOAT_OOB_FILL_NONE);
}

// ---------------- launch ----------------
extern "C" void kernel_launch(void* const* d_in, const int* in_sizes, int n_in,
                              void* d_out, int out_size)
{
    const float* x  = (const float*)d_in[0];
    const float* Wq = (const float*)d_in[1];
    const float* bq = (const float*)d_in[2];
    const float* Wk = (const float*)d_in[3];
    const float* bk = (const float*)d_in[4];
    const float* Wv = (const float*)d_in[5];
    const float* bv = (const float*)d_in[6];
    float* out = (float*)d_out;

    void *xh, *wqt, *wkt, *wvt, *q, *k, *vt, *s, *p;
    cudaGetSymbolAddress(&xh, g_xh);
    cudaGetSymbolAddress(&wqt, g_wqt); cudaGetSymbolAddress(&wkt, g_wkt); cudaGetSymbolAddress(&wvt, g_wvt);
    cudaGetSymbolAddress(&q, g_q); cudaGetSymbolAddress(&k, g_k);
    cudaGetSymbolAddress(&vt, g_vt);
    cudaGetSymbolAddress(&s, g_s); cudaGetSymbolAddress(&p, g_p);

    EncodeFn enc = nullptr;
    {
        void* fp = nullptr;
        cudaDriverEntryPointQueryResult qr;
        cudaGetDriverEntryPointByVersion("cuTensorMapEncodeTiled", &fp, 12000,
                                         cudaEnableDefault, &qr);
        enc = (EncodeFn)fp;
    }
    CUtensorMap tm_x, tm_wq, tm_wk, tm_wv, tm_q, tm_k, tm_p, tm_vt;
    make2d_h(enc, &tm_x,  xh,  8192, 1024);
    make2d_h(enc, &tm_wq, wqt, 1024, 1024);
    make2d_h(enc, &tm_wk, wkt, 1024, 1024);
    make2d_h(enc, &tm_wv, wvt, 1024, 1024);
    make2d_h(enc, &tm_q,  q,   8192, 1024);
    make2d_h(enc, &tm_k,  k,   8192, 1024);
    make2d_h(enc, &tm_p,  p,   8192, 2048);
    make2d_h(enc, &tm_vt, vt,  4096, 2048);

    cudaFuncSetAttribute(proj_qkv, cudaFuncAttributeMaxDynamicSharedMemorySize, DSMEM);
    cudaFuncSetAttribute(gemm_tma, cudaFuncAttributeMaxDynamicSharedMemorySize, DSMEM);

    const int MQ = BATCH * SEQ; // 8192

    // launch 0: convert x -> fp16
    cvt_kernel<<<MQ * DMODEL / 4 / 256, 256>>>((const float4*)x, (uint2*)xh, MQ * DMODEL / 4);

    // launch 1: transpose + convert all weights
    dim3 gw(DMODEL / 32, DMODEL / 32, 3);
    wtrans3_kernel<<<gw, 256>>>(Wq, Wk, Wv, (__half*)wqt, (__half*)wkt, (__half*)wvt);

    // launch 2: merged QKV projections (z = q/k/v)
    dim3 gp(DMODEL / 128, MQ / 128, 3);
    proj_qkv<<<gp, 256, DSMEM>>>(tm_x, tm_wq, tm_wk, tm_wv, bq, bk, bv,
                                 (__half*)q, (__half*)k, (__half*)vt);

    // launch 3: scores = Q K^T / 32, batched over z
    dim3 gs(SEQ / 128, SEQ / 128, BATCH);
    gemm_tma<<<gs, 256, DSMEM>>>(tm_q, tm_k, (float*)s, SEQ,
                                 (long long)SEQ * SEQ, 0.03125f, DMODEL, SEQ, SEQ);

    // launch 4: softmax
    softmax_kernel<<<BATCH * SEQ, 256>>>((const float*)s, (__half*)p);

    // launch 5 (profiled): out = P V
    dim3 go(DMODEL / 128, SEQ / 128, BATCH);
    gemm_tma<<<go, 256, DSMEM>>>(tm_p, tm_vt, out, DMODEL,
                                 (long long)SEQ * DMODEL, 1.0f, SEQ, SEQ, DMODEL);
}